// round 6
// baseline (speedup 1.0000x reference)
#include <cuda_runtime.h>
#include <cuda_fp16.h>
#include <cfloat>

#define NN   8192
#define FEA  192
#define HID  256
#define CLS  1000
#define CLSP 1024
#define KNB  9
#define NCAND 20
#define KSTR 512
#define QS   24.0f          // int8 quant scale
#define INV2 (2.0f / (QS * QS))

typedef unsigned int u32;
typedef unsigned short u16;
typedef unsigned long long u64;
typedef __half f16;

// ---------------- scratch ----------------------------------------------------
__device__ float g_sq[NN];
__device__ __align__(16) char g_xq[NN * FEA];      // int8 quantized x
__device__ __half g_Dh[(long long)NN * NN];        // 128 MB approx distances
__device__ int   g_idx[NN * KNB];
__device__ f16   g_c0h[NN * KSTR];
__device__ f16   g_c1h[NN * KSTR];
__device__ f16   g_w0h[256 * 384],  g_w0l[256 * 384];
__device__ f16   g_w1h[256 * 512],  g_w1l[256 * 512];
__device__ f16   g_w2h[1024 * 512], g_w2l[1024 * 512];
__device__ float g_h1[NN * HID];
__device__ float g_h2[NN * HID];
__device__ float g_h3[NN * CLSP];

// ---------------- helpers ----------------------------------------------------
__device__ __forceinline__ u32 s2u(const void* p) {
    u32 a;
    asm("{.reg .u64 t; cvta.to.shared.u64 t, %1; cvt.u32.u64 %0, t;}" : "=r"(a) : "l"(p));
    return a;
}
__device__ __forceinline__ void cpa16(u32 dst, const void* src) {
    asm volatile("cp.async.cg.shared.global [%0], [%1], 16;" :: "r"(dst), "l"(src));
}
__device__ __forceinline__ void ldsm4(u32* r, u32 addr) {
    asm volatile("ldmatrix.sync.aligned.m8n8.x4.shared.b16 {%0,%1,%2,%3}, [%4];"
        : "=r"(r[0]), "=r"(r[1]), "=r"(r[2]), "=r"(r[3]) : "r"(addr));
}
__device__ __forceinline__ void mma16816(float* c, const u32* a, const u32* b) {
    asm volatile("mma.sync.aligned.m16n8k16.row.col.f32.f16.f16.f32 "
        "{%0,%1,%2,%3},{%4,%5,%6,%7},{%8,%9},{%0,%1,%2,%3};"
        : "+f"(c[0]), "+f"(c[1]), "+f"(c[2]), "+f"(c[3])
        : "r"(a[0]), "r"(a[1]), "r"(a[2]), "r"(a[3]), "r"(b[0]), "r"(b[1]));
}
__device__ __forceinline__ void imma16832(int* c, const u32* a, const u32* b) {
    asm volatile("mma.sync.aligned.m16n8k32.row.col.s32.s8.s8.s32 "
        "{%0,%1,%2,%3},{%4,%5,%6,%7},{%8,%9},{%0,%1,%2,%3};"
        : "+r"(c[0]), "+r"(c[1]), "+r"(c[2]), "+r"(c[3])
        : "r"(a[0]), "r"(a[1]), "r"(a[2]), "r"(a[3]), "r"(b[0]), "r"(b[1]));
}
__device__ __forceinline__ void spltw(float v, f16& h, f16& l) {
    h = __float2half_rn(v);
    l = __float2half_rn(v - __half2float(h));
}

// fp16 tile loader: [128 rows x 32 k] (row stride 40 halfs = 80B)
__device__ __forceinline__ void ldtile(u32 dstb, const f16* g, int row0, int ld, int k0, int t) {
    #pragma unroll
    for (int q = 0; q < 2; q++) {
        int id = t * 2 + q;
        int row = id >> 2, kq = id & 3;
        cpa16(dstb + row * 80 + kq * 16, g + (size_t)(row0 + row) * ld + k0 + kq * 8);
    }
}

#define TB 10240     // fp16 tile: 128*40*2 bytes
#define I8STR 208    // int8 tile row stride (13 x 16B -> conflict-free ldmatrix)

// ---------------- small kernels ----------------------------------------------
__global__ void sq_kernel(const float* __restrict__ x) {
    int warp = (blockIdx.x * blockDim.x + threadIdx.x) >> 5;
    int lane = threadIdx.x & 31;
    if (warp >= NN) return;
    const float* r = x + (size_t)warp * FEA;
    float s = 0.f;
    for (int c = lane; c < FEA; c += 32) { float v = r[c]; s += v * v; }
    #pragma unroll
    for (int o = 16; o; o >>= 1) s += __shfl_xor_sync(0xffffffffu, s, o);
    if (lane == 0) g_sq[warp] = s;
}

// fp16 pack for layer-0 self features + int8 quantization
__global__ void xprep_kernel(const float* __restrict__ x) {
    int g = blockIdx.x * 256 + threadIdx.x;          // 4-element groups
    if (g >= NN * FEA / 4) return;
    int r = g / 48, c4 = (g % 48) * 4;
    float4 v = *(const float4*)(x + (size_t)r * FEA + c4);
    __half2 p0; p0.x = __float2half_rn(v.x); p0.y = __float2half_rn(v.y);
    __half2 p1; p1.x = __float2half_rn(v.z); p1.y = __float2half_rn(v.w);
    size_t off = (size_t)r * KSTR + 192 + c4;
    *(__half2*)(g_c0h + off)     = p0;
    *(__half2*)(g_c0h + off + 2) = p1;
    char4 q;
    q.x = (char)max(-127, min(127, __float2int_rn(v.x * QS)));
    q.y = (char)max(-127, min(127, __float2int_rn(v.y * QS)));
    q.z = (char)max(-127, min(127, __float2int_rn(v.z * QS)));
    q.w = (char)max(-127, min(127, __float2int_rn(v.w * QS)));
    *(char4*)(g_xq + (size_t)r * FEA + c4) = q;
}

__global__ void wt_build01(const float* __restrict__ Wl0, const float* __restrict__ Wr0,
                           const float* __restrict__ Wl1, const float* __restrict__ Wr1) {
    int layer = blockIdx.y;
    const float* Wl = layer ? Wl1 : Wl0;
    const float* Wr = layer ? Wr1 : Wr0;
    f16* WTh = layer ? g_w1h : g_w0h;
    f16* WTl = layer ? g_w1l : g_w0l;
    int K1 = layer ? 256 : 192;
    int Ktot = 2 * K1;
    int total = 256 * Ktot;
    int idx = blockIdx.x * 256 + threadIdx.x;
    if (idx >= total) return;
    int k = idx % Ktot;
    int n = idx / Ktot;
    float v = (k < K1) ? Wl[(size_t)k * HID + n] : Wr[(size_t)(k - K1) * HID + n];
    f16 h, l; spltw(v, h, l);
    WTh[idx] = h; WTl[idx] = l;
}

__global__ void wt_build2(const float* __restrict__ Wl, const float* __restrict__ Wr) {
    int idx = blockIdx.x * 256 + threadIdx.x;
    if (idx >= 1024 * 512) return;
    int n = idx / 512, k = idx % 512;
    float v = 0.f;
    if (n < CLS) v = (k < 256) ? Wl[(size_t)k * CLS + n] : Wr[(size_t)(k - 256) * CLS + n];
    f16 h, l; spltw(v, h, l);
    g_w2h[idx] = h; g_w2l[idx] = l;
}

// ---------------- int8 distance screen GEMM ------------------------------------
__global__ __launch_bounds__(256, 2) void dist_i8(const char* __restrict__ xq) {
    // triangular unrank: pair index -> (bi <= bj)
    int tp = blockIdx.x;
    int bj = (int)((sqrtf(8.f * tp + 1.f) - 1.f) * 0.5f);
    while ((bj + 1) * (bj + 2) / 2 <= tp) bj++;
    while (bj * (bj + 1) / 2 > tp) bj--;
    int bi = tp - bj * (bj + 1) / 2;

    extern __shared__ __align__(16) char smem[];
    u32 sb = s2u(smem);
    u32 sbA = sb, sbB = sb + 128 * I8STR;
    int t = threadIdx.x, lane = t & 31, warp = t >> 5;
    int wm = warp & 1, wn = warp >> 1;

    // load both int8 tiles (full K=192): 128 rows x 12 x 16B each
    #pragma unroll
    for (int q = 0; q < 6; q++) {
        int id = t * 6 + q;
        int row = id / 12, c = id % 12;
        cpa16(sbA + row * I8STR + c * 16, xq + (size_t)(bi * 128 + row) * FEA + c * 16);
    }
    #pragma unroll
    for (int q = 0; q < 6; q++) {
        int id = t * 6 + q;
        int row = id / 12, c = id % 12;
        cpa16(sbB + row * I8STR + c * 16, xq + (size_t)(bj * 128 + row) * FEA + c * 16);
    }
    asm volatile("cp.async.commit_group;");
    asm volatile("cp.async.wait_group 0;");
    __syncthreads();

    int acc[4][4][4] = {};
    #pragma unroll
    for (int ks = 0; ks < 6; ks++) {
        int kb = ks * 32;
        u32 A[4][4], B[4][2];
        #pragma unroll
        for (int mt = 0; mt < 4; mt++) {
            u32 ro = (u32)((wm * 64 + mt * 16 + (lane & 15)) * I8STR + kb + (lane >> 4) * 16);
            ldsm4(A[mt], sbA + ro);
        }
        #pragma unroll
        for (int np = 0; np < 2; np++) {
            u32 ro = (u32)((wn * 32 + np * 16 + (lane >> 4) * 8 + (lane & 7)) * I8STR
                           + kb + ((lane >> 3) & 1) * 16);
            u32 r[4];
            ldsm4(r, sbB + ro);
            B[2 * np][0] = r[0]; B[2 * np][1] = r[1];
            B[2 * np + 1][0] = r[2]; B[2 * np + 1][1] = r[3];
        }
        #pragma unroll
        for (int mt = 0; mt < 4; mt++)
            #pragma unroll
            for (int nt = 0; nt < 4; nt++)
                imma16832(acc[mt][nt], A[mt], B[nt]);
    }
    __syncthreads();

    // epilogue: d = sq_i + sq_j - (2/s^2)*acc; stage fp16 tiles, write coalesced
    u16* sD = (u16*)smem;            // [128][136]
    u16* sT = sD + 128 * 136;
    bool diag = (bi == bj);
    #pragma unroll
    for (int mt = 0; mt < 4; mt++) {
        int rl0 = wm * 64 + mt * 16 + (lane >> 2);
        #pragma unroll
        for (int nt = 0; nt < 4; nt++) {
            int cl = wn * 32 + nt * 8 + (lane & 3) * 2;
            float sqc0 = g_sq[bj * 128 + cl], sqc1 = g_sq[bj * 128 + cl + 1];
            #pragma unroll
            for (int h = 0; h < 2; h++) {
                int rl = rl0 + h * 8;
                float sr = g_sq[bi * 128 + rl];
                float d0 = sr + sqc0 - INV2 * (float)acc[mt][nt][2 * h + 0];
                float d1 = sr + sqc1 - INV2 * (float)acc[mt][nt][2 * h + 1];
                u16 b0 = __half_as_ushort(__float2half_rn(d0));
                u16 b1 = __half_as_ushort(__float2half_rn(d1));
                sD[rl * 136 + cl] = b0;
                sD[rl * 136 + cl + 1] = b1;
                if (!diag) {
                    sT[cl * 136 + rl] = b0;
                    sT[(cl + 1) * 136 + rl] = b1;
                }
            }
        }
    }
    __syncthreads();
    u16* gD = (u16*)g_Dh;
    for (int e = t; e < 128 * 16; e += 256) {
        int r = e >> 4, c8 = (e & 15) * 8;
        uint4 v = *(uint4*)&sD[r * 136 + c8];
        *(uint4*)(gD + (size_t)(bi * 128 + r) * NN + bj * 128 + c8) = v;
    }
    if (!diag) {
        for (int e = t; e < 128 * 16; e += 256) {
            int r = e >> 4, c8 = (e & 15) * 8;
            uint4 v = *(uint4*)&sT[r * 136 + c8];
            *(uint4*)(gD + (size_t)(bj * 128 + r) * NN + bi * 128 + c8) = v;
        }
    }
}

// ---------------- top-20 candidates + exact fp32 refine to top-9 --------------
__global__ __launch_bounds__(256) void topk_refine(const float* __restrict__ x) {
    int i = blockIdx.x;
    int t = threadIdx.x, lane = t & 31, wid = t >> 5;
    __shared__ u16 skey[NN];
    __shared__ u32 wmin[8];
    __shared__ u32 bcast;
    __shared__ int cand[NCAND];
    __shared__ float cdist[NCAND];
    __shared__ float xi[FEA];

    const u16* row = (const u16*)(g_Dh + (size_t)i * NN);
    int j0 = t * 32;
    u32 mylm = 0xFFFFFFFFu;
    #pragma unroll
    for (int q = 0; q < 4; q++) {
        uint4 v = __ldg((const uint4*)(row + j0 + q * 8));
        u32 w[4] = {v.x, v.y, v.z, v.w};
        #pragma unroll
        for (int p = 0; p < 4; p++) {
            #pragma unroll
            for (int hh = 0; hh < 2; hh++) {
                u16 hb = (u16)(w[p] >> (16 * hh));
                u16 key = (u16)(hb ^ ((hb & 0x8000) ? 0xFFFFu : 0x8000u));
                int j = j0 + q * 8 + p * 2 + hh;
                skey[j] = key;
                u32 pk = ((u32)key << 16) | (u32)j;
                mylm = min(mylm, pk);
            }
        }
    }

    for (int r = 0; r < NCAND; r++) {
        u32 v = mylm;
        #pragma unroll
        for (int o = 16; o; o >>= 1) v = min(v, __shfl_xor_sync(0xffffffffu, v, o));
        if (lane == 0) wmin[wid] = v;
        __syncthreads();
        if (t < 8) {
            u32 u = wmin[t];
            #pragma unroll
            for (int o = 4; o; o >>= 1) u = min(u, __shfl_xor_sync(0xffu, u, o));
            if (t == 0) { bcast = u; cand[r] = (int)(u & 0xFFFFu); }
        }
        __syncthreads();
        int jstar = (int)(bcast & 0xFFFFu);
        if ((jstar >> 5) == t) {
            skey[jstar] = 0xFFFFu;
            u32 nm = 0xFFFFFFFFu;
            #pragma unroll
            for (int q = 0; q < 32; q++) {
                int j = j0 + q;
                nm = min(nm, ((u32)skey[j] << 16) | (u32)j);
            }
            mylm = nm;
        }
        __syncthreads();
    }

    // exact fp32 refine
    for (int d = t; d < FEA; d += 256) xi[d] = __ldg(x + (size_t)i * FEA + d);
    __syncthreads();
    #pragma unroll
    for (int q = 0; q < 3; q++) {
        int c = wid + q * 8;
        if (c < NCAND) {
            int j = cand[c];
            const float* xj = x + (size_t)j * FEA;
            float s = 0.f;
            #pragma unroll
            for (int d = lane; d < FEA; d += 32) s = fmaf(xi[d], __ldg(xj + d), s);
            #pragma unroll
            for (int o = 16; o; o >>= 1) s += __shfl_xor_sync(0xffffffffu, s, o);
            if (lane == 0) cdist[c] = g_sq[i] + g_sq[j] - 2.f * s;
        }
    }
    __syncthreads();
    if (t == 0) {
        u64 keys[NCAND];
        #pragma unroll
        for (int c = 0; c < NCAND; c++) {
            u32 b = __float_as_uint(cdist[c]);
            b ^= (b & 0x80000000u) ? 0xFFFFFFFFu : 0x80000000u;
            keys[c] = ((u64)b << 32) | (u32)cand[c];
        }
        #pragma unroll
        for (int r = 0; r < KNB; r++) {
            u64 best = keys[0]; int bs = 0;
            #pragma unroll
            for (int c = 1; c < NCAND; c++)
                if (keys[c] < best) { best = keys[c]; bs = c; }
            g_idx[i * KNB + r] = (int)(best & 0xFFFFFFFFull);
            keys[bs] = ~0ull;
        }
    }
}

// ---------------- gather + mean -> fp16 ----------------------------------------
__global__ void gather_split(const float* __restrict__ h, int C, f16* __restrict__ oh) {
    int row = blockIdx.x * 4 + threadIdx.y;
    int c4 = threadIdx.x * 4;
    const int* idp = g_idx + row * KNB;
    float4 s = make_float4(0.f, 0.f, 0.f, 0.f);
    #pragma unroll
    for (int j = 0; j < KNB; j++) {
        float4 v = __ldg((const float4*)(h + (size_t)idp[j] * C + c4));
        s.x += v.x; s.y += v.y; s.z += v.z; s.w += v.w;
    }
    const float inv = 1.0f / 9.0f;
    size_t off = (size_t)row * KSTR + c4;
    __half2 p0; p0.x = __float2half_rn(s.x * inv); p0.y = __float2half_rn(s.y * inv);
    __half2 p1; p1.x = __float2half_rn(s.z * inv); p1.y = __float2half_rn(s.w * inv);
    *(__half2*)(oh + off)     = p0;
    *(__half2*)(oh + off + 2) = p1;
}

// ---------------- SAGE dual-GEMM: relu(A@[Wl;Wr] + b), fp16 2-term -------------
__global__ __launch_bounds__(256, 1) void sage_mma(
    const f16* __restrict__ Ah, int Ktot,
    const f16* __restrict__ Bh, const f16* __restrict__ Bl,
    const float* __restrict__ bias, int Nbias,
    float* __restrict__ O, int Nstr,
    f16* __restrict__ Sh)
{
    int bn = blockIdx.x, bm = blockIdx.y;
    extern __shared__ __align__(16) char smem[];
    u32 sb = s2u(smem);
    int t = threadIdx.x, lane = t & 31, warp = t >> 5;
    int wm = warp & 1, wn = warp >> 1;

    float acc[4][4][4] = {};

    int nc = Ktot / 32;
    ldtile(sb + 0 * TB, Ah, bm * 128, KSTR, 0, t);
    ldtile(sb + 1 * TB, Bh, bn * 128, Ktot, 0, t);
    ldtile(sb + 2 * TB, Bl, bn * 128, Ktot, 0, t);
    asm volatile("cp.async.commit_group;");

    for (int c = 0; c < nc; c++) {
        if (c + 1 < nc) {
            u32 bb = sb + ((c + 1) & 1) * 3 * TB;
            int k0 = (c + 1) * 32;
            ldtile(bb + 0 * TB, Ah, bm * 128, KSTR, k0, t);
            ldtile(bb + 1 * TB, Bh, bn * 128, Ktot, k0, t);
            ldtile(bb + 2 * TB, Bl, bn * 128, Ktot, k0, t);
            asm volatile("cp.async.commit_group;");
            asm volatile("cp.async.wait_group 1;");
        } else {
            asm volatile("cp.async.wait_group 0;");
        }
        __syncthreads();
        u32 base = sb + (c & 1) * 3 * TB;
        u32 aH = base, bH = base + TB, bL = base + 2 * TB;
        #pragma unroll
        for (int kk = 0; kk < 32; kk += 16) {
            u32 AH[4][4], BH[4][2], BL[4][2];
            #pragma unroll
            for (int mt = 0; mt < 4; mt++) {
                u32 ro = (u32)((wm * 64 + mt * 16 + (lane & 15)) * 80 + (kk + (lane >> 4) * 8) * 2);
                ldsm4(AH[mt], aH + ro);
            }
            #pragma unroll
            for (int np = 0; np < 2; np++) {
                u32 ro = (u32)((wn * 32 + np * 16 + ((lane >> 4) * 8) + (lane & 7)) * 80
                               + (kk + ((lane >> 3) & 1) * 8) * 2);
                u32 r[4];
                ldsm4(r, bH + ro);
                BH[2 * np][0] = r[0]; BH[2 * np][1] = r[1];
                BH[2 * np + 1][0] = r[2]; BH[2 * np + 1][1] = r[3];
                ldsm4(r, bL + ro);
                BL[2 * np][0] = r[0]; BL[2 * np][1] = r[1];
                BL[2 * np + 1][0] = r[2]; BL[2 * np + 1][1] = r[3];
            }
            #pragma unroll
            for (int mt = 0; mt < 4; mt++)
                #pragma unroll
                for (int nt = 0; nt < 4; nt++) {
                    mma16816(acc[mt][nt], AH[mt], BH[nt]);
                    mma16816(acc[mt][nt], AH[mt], BL[nt]);
                }
        }
        __syncthreads();
    }

    #pragma unroll
    for (int mt = 0; mt < 4; mt++) {
        int rl0 = wm * 64 + mt * 16 + (lane >> 2);
        #pragma unroll
        for (int nt = 0; nt < 4; nt++) {
            int cl = wn * 32 + nt * 8 + (lane & 3) * 2;
            int col = bn * 128 + cl;
            float b0 = (col < Nbias) ? bias[col] : 0.f;
            float b1 = (col + 1 < Nbias) ? bias[col + 1] : 0.f;
            #pragma unroll
            for (int h = 0; h < 2; h++) {
                int row = bm * 128 + rl0 + h * 8;
                float v0 = fmaxf(acc[mt][nt][2 * h + 0] + b0, 0.f);
                float v1 = fmaxf(acc[mt][nt][2 * h + 1] + b1, 0.f);
                *(float2*)(O + (size_t)row * Nstr + col) = make_float2(v0, v1);
                if (Sh) {
                    __half2 p; p.x = __float2half_rn(v0); p.y = __float2half_rn(v1);
                    *(__half2*)(Sh + (size_t)row * KSTR + col) = p;
                }
            }
        }
    }
}

// ---------------- mean pool ----------------------------------------------------
__global__ void pool_kernel(const float* __restrict__ h3, float* __restrict__ out) {
    int b = blockIdx.x;
    int chunk = blockIdx.y;
    int t = threadIdx.x;
    if (t >= 125) return;
    int o = chunk * 125 + t;
    const float* p = h3 + (size_t)(b * 512) * CLSP + o;
    float s = 0.f;
    for (int r = 0; r < 512; r++) s += p[(size_t)r * CLSP];
    out[b * CLS + o] = s * (1.0f / 512.0f);
}

// ---------------- launch --------------------------------------------------------
#define DIST_SMEM (128 * 136 * 2 * 2)   // 69632 (>= 2*128*208 mainloop tiles)
#define SAGE_SMEM (6 * TB)              // 61440

extern "C" void kernel_launch(void* const* d_in, const int* in_sizes, int n_in,
                              void* d_out, int out_size) {
    const float* x   = (const float*)d_in[0];
    const float* wl0 = (const float*)d_in[1];
    const float* bl0 = (const float*)d_in[2];
    const float* wr0 = (const float*)d_in[3];
    const float* wl1 = (const float*)d_in[4];
    const float* bl1 = (const float*)d_in[5];
    const float* wr1 = (const float*)d_in[6];
    const float* wl2 = (const float*)d_in[7];
    const float* bl2 = (const float*)d_in[8];
    const float* wr2 = (const float*)d_in[9];
    float* out = (float*)d_out;

    f16 *c0h, *c1h, *w0h, *w0l, *w1h, *w1l, *w2h, *w2l;
    float *h1, *h2, *h3;
    char* xq;
    cudaGetSymbolAddress((void**)&c0h, g_c0h);
    cudaGetSymbolAddress((void**)&c1h, g_c1h);
    cudaGetSymbolAddress((void**)&w0h, g_w0h);
    cudaGetSymbolAddress((void**)&w0l, g_w0l);
    cudaGetSymbolAddress((void**)&w1h, g_w1h);
    cudaGetSymbolAddress((void**)&w1l, g_w1l);
    cudaGetSymbolAddress((void**)&w2h, g_w2h);
    cudaGetSymbolAddress((void**)&w2l, g_w2l);
    cudaGetSymbolAddress((void**)&h1, g_h1);
    cudaGetSymbolAddress((void**)&h2, g_h2);
    cudaGetSymbolAddress((void**)&h3, g_h3);
    cudaGetSymbolAddress((void**)&xq, g_xq);

    cudaFuncSetAttribute(dist_i8, cudaFuncAttributeMaxDynamicSharedMemorySize, DIST_SMEM);
    cudaFuncSetAttribute(sage_mma, cudaFuncAttributeMaxDynamicSharedMemorySize, SAGE_SMEM);

    sq_kernel<<<NN / 8, 256>>>(x);                                   // 1
    xprep_kernel<<<(NN * FEA / 4 + 255) / 256, 256>>>(x);            // 2
    wt_build01<<<dim3(512, 2), 256>>>(wl0, wr0, wl1, wr1);           // 3
    dist_i8<<<2080, 256, DIST_SMEM>>>(xq);                           // 4 (profiled)
    wt_build2<<<(1024 * 512 + 255) / 256, 256>>>(wl2, wr2);          // 5
    topk_refine<<<NN, 256>>>(x);                                     // 6

    // layer 0: [agg(x) | x], K=384
    gather_split<<<NN / 4, dim3(FEA / 4, 4)>>>(x, FEA, c0h);
    sage_mma<<<dim3(2, 64), 256, SAGE_SMEM>>>(c0h, 384, w0h, w0l, bl0, HID,
                                              h1, HID, c1h + 256);
    // layer 1: [agg(h1) | h1], K=512
    gather_split<<<NN / 4, dim3(HID / 4, 4)>>>(h1, HID, c1h);
    sage_mma<<<dim3(2, 64), 256, SAGE_SMEM>>>(c1h, 512, w1h, w1l, bl1, HID,
                                              h2, HID, c0h + 256);
    // layer 2: [agg(h2) | h2], K=512, N padded 1024
    gather_split<<<NN / 4, dim3(HID / 4, 4)>>>(h2, HID, c0h);
    sage_mma<<<dim3(8, 64), 256, SAGE_SMEM>>>(c0h, 512, w2h, w2l, bl2, CLS,
                                              h3, CLSP, (f16*)nullptr);

    pool_kernel<<<dim3(16, 8), 128>>>(h3, out);
}

// round 7
// speedup vs baseline: 1.1547x; 1.1547x over previous
#include <cuda_runtime.h>
#include <cuda_fp16.h>
#include <cfloat>

#define NN   8192
#define FEA  192
#define HID  256
#define CLS  1000
#define KNB  9
#define NCAND 16
#define KSTR 512
#define BATCH 16

typedef unsigned int u32;
typedef unsigned short u16;
typedef unsigned long long u64;
typedef __half f16;

// ---------------- scratch ----------------------------------------------------
__device__ float g_sq[NN];
__device__ __half g_Dh[(long long)NN * NN];        // 128 MB approx distances
__device__ int   g_idx[NN * KNB];
__device__ f16   g_c0h[NN * KSTR];                 // cat buffer 0: [agg | self]
__device__ f16   g_c1h[NN * KSTR];                 // cat buffer 1
__device__ f16   g_w0h[256 * 384],  g_w0l[256 * 384];
__device__ f16   g_w1h[256 * 512],  g_w1l[256 * 512];
__device__ f16   g_w2h[1024 * 512], g_w2l[1024 * 512];
__device__ float g_part[512 * 128];                // layer2 pool partials [bm*8+bn][128]

// ---------------- helpers ----------------------------------------------------
__device__ __forceinline__ u32 s2u(const void* p) {
    u32 a;
    asm("{.reg .u64 t; cvta.to.shared.u64 t, %1; cvt.u32.u64 %0, t;}" : "=r"(a) : "l"(p));
    return a;
}
__device__ __forceinline__ void cpa16(u32 dst, const void* src) {
    asm volatile("cp.async.cg.shared.global [%0], [%1], 16;" :: "r"(dst), "l"(src));
}
__device__ __forceinline__ void ldsm4(u32* r, u32 addr) {
    asm volatile("ldmatrix.sync.aligned.m8n8.x4.shared.b16 {%0,%1,%2,%3}, [%4];"
        : "=r"(r[0]), "=r"(r[1]), "=r"(r[2]), "=r"(r[3]) : "r"(addr));
}
__device__ __forceinline__ void mma16816(float* c, const u32* a, const u32* b) {
    asm volatile("mma.sync.aligned.m16n8k16.row.col.f32.f16.f16.f32 "
        "{%0,%1,%2,%3},{%4,%5,%6,%7},{%8,%9},{%0,%1,%2,%3};"
        : "+f"(c[0]), "+f"(c[1]), "+f"(c[2]), "+f"(c[3])
        : "r"(a[0]), "r"(a[1]), "r"(a[2]), "r"(a[3]), "r"(b[0]), "r"(b[1]));
}
__device__ __forceinline__ void spltw(float v, f16& h, f16& l) {
    h = __float2half_rn(v);
    l = __float2half_rn(v - __half2float(h));
}

// fp16 tile loader: [128 rows x 32 k] (row stride 40 halfs = 80B)
__device__ __forceinline__ void ldtile(u32 dstb, const f16* g, int row0, int ld, int k0, int t) {
    #pragma unroll
    for (int q = 0; q < 2; q++) {
        int id = t * 2 + q;
        int row = id >> 2, kq = id & 3;
        cpa16(dstb + row * 80 + kq * 16, g + (size_t)(row0 + row) * ld + k0 + kq * 8);
    }
}

#define TB 10240     // fp16 tile: 128*40*2 bytes

// ---------------- small kernels ----------------------------------------------
__global__ void sq_kernel(const float* __restrict__ x) {
    int warp = (blockIdx.x * blockDim.x + threadIdx.x) >> 5;
    int lane = threadIdx.x & 31;
    if (warp >= NN) return;
    const float* r = x + (size_t)warp * FEA;
    float s = 0.f;
    for (int c = lane; c < FEA; c += 32) { float v = r[c]; s += v * v; }
    #pragma unroll
    for (int o = 16; o; o >>= 1) s += __shfl_xor_sync(0xffffffffu, s, o);
    if (lane == 0) g_sq[warp] = s;
}

// fp16 pack of x into cat buffer 0 self region (cols 192..383)
__global__ void xprep_kernel(const float* __restrict__ x) {
    int g = blockIdx.x * 256 + threadIdx.x;          // 4-element groups
    if (g >= NN * FEA / 4) return;
    int r = g / 48, c4 = (g % 48) * 4;
    float4 v = *(const float4*)(x + (size_t)r * FEA + c4);
    __half2 p0; p0.x = __float2half_rn(v.x); p0.y = __float2half_rn(v.y);
    __half2 p1; p1.x = __float2half_rn(v.z); p1.y = __float2half_rn(v.w);
    size_t off = (size_t)r * KSTR + 192 + c4;
    *(__half2*)(g_c0h + off)     = p0;
    *(__half2*)(g_c0h + off + 2) = p1;
}

__global__ void wt_build01(const float* __restrict__ Wl0, const float* __restrict__ Wr0,
                           const float* __restrict__ Wl1, const float* __restrict__ Wr1) {
    int layer = blockIdx.y;
    const float* Wl = layer ? Wl1 : Wl0;
    const float* Wr = layer ? Wr1 : Wr0;
    f16* WTh = layer ? g_w1h : g_w0h;
    f16* WTl = layer ? g_w1l : g_w0l;
    int K1 = layer ? 256 : 192;
    int Ktot = 2 * K1;
    int total = 256 * Ktot;
    int idx = blockIdx.x * 256 + threadIdx.x;
    if (idx >= total) return;
    int k = idx % Ktot;
    int n = idx / Ktot;
    float v = (k < K1) ? Wl[(size_t)k * HID + n] : Wr[(size_t)(k - K1) * HID + n];
    f16 h, l; spltw(v, h, l);
    WTh[idx] = h; WTl[idx] = l;
}

__global__ void wt_build2(const float* __restrict__ Wl, const float* __restrict__ Wr) {
    int idx = blockIdx.x * 256 + threadIdx.x;
    if (idx >= 1024 * 512) return;
    int n = idx / 512, k = idx % 512;
    float v = 0.f;
    if (n < CLS) v = (k < 256) ? Wl[(size_t)k * CLS + n] : Wr[(size_t)(k - 256) * CLS + n];
    f16 h, l; spltw(v, h, l);
    g_w2h[idx] = h; g_w2l[idx] = l;
}

// ---------------- fp16 distance screen GEMM (triangular grid) -----------------
__global__ __launch_bounds__(256, 1) void dist_half(const f16* __restrict__ Xh) {
    // triangular unrank: pair index -> (bi <= bj)
    int tp = blockIdx.x;
    int bj = (int)((sqrtf(8.f * tp + 1.f) - 1.f) * 0.5f);
    while ((bj + 1) * (bj + 2) / 2 <= tp) bj++;
    while (bj * (bj + 1) / 2 > tp) bj--;
    int bi = tp - bj * (bj + 1) / 2;

    extern __shared__ __align__(16) char smem[];
    u32 sb = s2u(smem);
    int t = threadIdx.x, lane = t & 31, warp = t >> 5;
    int wm = warp & 1, wn = warp >> 1;

    float acc[4][4][4] = {};

    const int NC = FEA / 32;   // 6
    ldtile(sb + 0 * TB, Xh, bi * 128, KSTR, 0, t);
    ldtile(sb + 1 * TB, Xh, bj * 128, KSTR, 0, t);
    asm volatile("cp.async.commit_group;");

    for (int c = 0; c < NC; c++) {
        if (c + 1 < NC) {
            u32 bb = sb + ((c + 1) & 1) * 2 * TB;
            int k0 = (c + 1) * 32;
            ldtile(bb + 0 * TB, Xh, bi * 128, KSTR, k0, t);
            ldtile(bb + 1 * TB, Xh, bj * 128, KSTR, k0, t);
            asm volatile("cp.async.commit_group;");
            asm volatile("cp.async.wait_group 1;");
        } else {
            asm volatile("cp.async.wait_group 0;");
        }
        __syncthreads();
        u32 base = sb + (c & 1) * 2 * TB;
        u32 aH = base, bH = base + TB;
        #pragma unroll
        for (int kk = 0; kk < 32; kk += 16) {
            u32 AH[4][4], BH[4][2];
            #pragma unroll
            for (int mt = 0; mt < 4; mt++) {
                u32 ro = (u32)((wm * 64 + mt * 16 + (lane & 15)) * 80 + (kk + (lane >> 4) * 8) * 2);
                ldsm4(AH[mt], aH + ro);
            }
            #pragma unroll
            for (int np = 0; np < 2; np++) {
                u32 ro = (u32)((wn * 32 + np * 16 + ((lane >> 4) * 8) + (lane & 7)) * 80
                               + (kk + ((lane >> 3) & 1) * 8) * 2);
                u32 r[4];
                ldsm4(r, bH + ro);
                BH[2 * np][0] = r[0]; BH[2 * np][1] = r[1];
                BH[2 * np + 1][0] = r[2]; BH[2 * np + 1][1] = r[3];
            }
            #pragma unroll
            for (int mt = 0; mt < 4; mt++)
                #pragma unroll
                for (int nt = 0; nt < 4; nt++)
                    mma16816(acc[mt][nt], AH[mt], BH[nt]);
        }
        __syncthreads();
    }

    // epilogue: stage both tiles as fp16 in smem, write coalesced
    u16* sD = (u16*)smem;            // [128][136]
    u16* sT = sD + 128 * 136;
    bool diag = (bi == bj);
    #pragma unroll
    for (int mt = 0; mt < 4; mt++) {
        int rl0 = wm * 64 + mt * 16 + (lane >> 2);
        #pragma unroll
        for (int nt = 0; nt < 4; nt++) {
            int cl = wn * 32 + nt * 8 + (lane & 3) * 2;
            float sqc0 = g_sq[bj * 128 + cl], sqc1 = g_sq[bj * 128 + cl + 1];
            #pragma unroll
            for (int h = 0; h < 2; h++) {
                int rl = rl0 + h * 8;
                float sr = g_sq[bi * 128 + rl];
                float d0 = sr + sqc0 - 2.f * acc[mt][nt][2 * h + 0];
                float d1 = sr + sqc1 - 2.f * acc[mt][nt][2 * h + 1];
                u16 b0 = __half_as_ushort(__float2half_rn(d0));
                u16 b1 = __half_as_ushort(__float2half_rn(d1));
                sD[rl * 136 + cl] = b0;
                sD[rl * 136 + cl + 1] = b1;
                if (!diag) {
                    sT[cl * 136 + rl] = b0;
                    sT[(cl + 1) * 136 + rl] = b1;
                }
            }
        }
    }
    __syncthreads();
    u16* gD = (u16*)g_Dh;
    for (int e = t; e < 128 * 16; e += 256) {
        int r = e >> 4, c8 = (e & 15) * 8;
        uint4 v = *(uint4*)&sD[r * 136 + c8];
        *(uint4*)(gD + (size_t)(bi * 128 + r) * NN + bj * 128 + c8) = v;
    }
    if (!diag) {
        for (int e = t; e < 128 * 16; e += 256) {
            int r = e >> 4, c8 = (e & 15) * 8;
            uint4 v = *(uint4*)&sT[r * 136 + c8];
            *(uint4*)(gD + (size_t)(bj * 128 + r) * NN + bi * 128 + c8) = v;
        }
    }
}

// ---------------- top-16 candidates + exact fp32 refine to top-9 --------------
__global__ __launch_bounds__(256) void topk_refine(const float* __restrict__ x) {
    int i = blockIdx.x;
    int t = threadIdx.x, lane = t & 31, wid = t >> 5;
    __shared__ u16 skey[NN];
    __shared__ u32 wmin[8];
    __shared__ u32 bcast;
    __shared__ int cand[NCAND];
    __shared__ float cdist[NCAND];
    __shared__ float xi[FEA];

    const u16* row = (const u16*)(g_Dh + (size_t)i * NN);
    int j0 = t * 32;
    u32 mylm = 0xFFFFFFFFu;
    #pragma unroll
    for (int q = 0; q < 4; q++) {
        uint4 v = __ldg((const uint4*)(row + j0 + q * 8));
        u32 w[4] = {v.x, v.y, v.z, v.w};
        #pragma unroll
        for (int p = 0; p < 4; p++) {
            #pragma unroll
            for (int hh = 0; hh < 2; hh++) {
                u16 hb = (u16)(w[p] >> (16 * hh));
                u16 key = (u16)(hb ^ ((hb & 0x8000) ? 0xFFFFu : 0x8000u));
                int j = j0 + q * 8 + p * 2 + hh;
                skey[j] = key;
                u32 pk = ((u32)key << 16) | (u32)j;
                mylm = min(mylm, pk);
            }
        }
    }

    for (int r = 0; r < NCAND; r++) {
        u32 v = mylm;
        #pragma unroll
        for (int o = 16; o; o >>= 1) v = min(v, __shfl_xor_sync(0xffffffffu, v, o));
        if (lane == 0) wmin[wid] = v;
        __syncthreads();
        if (t < 8) {
            u32 u = wmin[t];
            #pragma unroll
            for (int o = 4; o; o >>= 1) u = min(u, __shfl_xor_sync(0xffu, u, o));
            if (t == 0) { bcast = u; cand[r] = (int)(u & 0xFFFFu); }
        }
        __syncthreads();
        int jstar = (int)(bcast & 0xFFFFu);
        if ((jstar >> 5) == t) {
            skey[jstar] = 0xFFFFu;
            u32 nm = 0xFFFFFFFFu;
            #pragma unroll
            for (int q = 0; q < 32; q++) {
                int j = j0 + q;
                nm = min(nm, ((u32)skey[j] << 16) | (u32)j);
            }
            mylm = nm;
        }
        __syncthreads();
    }

    // exact fp32 refine
    for (int d = t; d < FEA; d += 256) xi[d] = __ldg(x + (size_t)i * FEA + d);
    __syncthreads();
    #pragma unroll
    for (int q = 0; q < NCAND / 8; q++) {
        int c = wid + q * 8;
        int j = cand[c];
        const float* xj = x + (size_t)j * FEA;
        float s = 0.f;
        #pragma unroll
        for (int d = lane; d < FEA; d += 32) s = fmaf(xi[d], __ldg(xj + d), s);
        #pragma unroll
        for (int o = 16; o; o >>= 1) s += __shfl_xor_sync(0xffffffffu, s, o);
        if (lane == 0) cdist[c] = g_sq[i] + g_sq[j] - 2.f * s;
    }
    __syncthreads();
    if (t == 0) {
        u64 keys[NCAND];
        #pragma unroll
        for (int c = 0; c < NCAND; c++) {
            u32 b = __float_as_uint(cdist[c]);
            b ^= (b & 0x80000000u) ? 0xFFFFFFFFu : 0x80000000u;
            keys[c] = ((u64)b << 32) | (u32)cand[c];
        }
        #pragma unroll
        for (int r = 0; r < KNB; r++) {
            u64 best = keys[0]; int bs = 0;
            #pragma unroll
            for (int c = 1; c < NCAND; c++)
                if (keys[c] < best) { best = keys[c]; bs = c; }
            g_idx[i * KNB + r] = (int)(best & 0xFFFFFFFFull);
            keys[bs] = ~0ull;
        }
    }
}

// ---------------- gather + mean from fp32 x (layer 0) --------------------------
__global__ void gather_x(const float* __restrict__ x, f16* __restrict__ oh) {
    int row = blockIdx.x * 4 + threadIdx.y;
    int c4 = threadIdx.x * 4;
    const int* idp = g_idx + row * KNB;
    float4 s = make_float4(0.f, 0.f, 0.f, 0.f);
    #pragma unroll
    for (int j = 0; j < KNB; j++) {
        float4 v = __ldg((const float4*)(x + (size_t)idp[j] * FEA + c4));
        s.x += v.x; s.y += v.y; s.z += v.z; s.w += v.w;
    }
    const float inv = 1.0f / 9.0f;
    size_t off = (size_t)row * KSTR + c4;
    __half2 p0; p0.x = __float2half_rn(s.x * inv); p0.y = __float2half_rn(s.y * inv);
    __half2 p1; p1.x = __float2half_rn(s.z * inv); p1.y = __float2half_rn(s.w * inv);
    *(__half2*)(oh + off)     = p0;
    *(__half2*)(oh + off + 2) = p1;
}

// ---------------- gather + mean from fp16 cat self (layers 1,2) ----------------
// reads cat[id*KSTR + 256 + c], writes cat[row*KSTR + c], c in [0,256)
__global__ void gather_f16(const f16* __restrict__ cat_self, f16* __restrict__ cat_agg) {
    int row = blockIdx.x * 8 + threadIdx.y;
    int c8 = threadIdx.x * 8;
    const int* idp = g_idx + row * KNB;
    float s[8] = {0.f, 0.f, 0.f, 0.f, 0.f, 0.f, 0.f, 0.f};
    #pragma unroll
    for (int j = 0; j < KNB; j++) {
        uint4 v = __ldg((const uint4*)(cat_self + (size_t)idp[j] * KSTR + c8));
        u32 w[4] = {v.x, v.y, v.z, v.w};
        #pragma unroll
        for (int p = 0; p < 4; p++) {
            float2 f = __half22float2(*(__half2*)&w[p]);
            s[2 * p] += f.x; s[2 * p + 1] += f.y;
        }
    }
    const float inv = 1.0f / 9.0f;
    u32 out[4];
    #pragma unroll
    for (int p = 0; p < 4; p++) {
        __half2 h; h.x = __float2half_rn(s[2 * p] * inv); h.y = __float2half_rn(s[2 * p + 1] * inv);
        out[p] = *(u32*)&h;
    }
    *(uint4*)(cat_agg + (size_t)row * KSTR + c8) = *(uint4*)out;
}

// ---------------- SAGE dual-GEMM: relu(A@[Wl;Wr] + b) --------------------------
// Sh != null: write fp16 to next cat buffer. part != null: pool partial sums.
__global__ __launch_bounds__(256, 1) void sage_mma(
    const f16* __restrict__ Ah, int Ktot,
    const f16* __restrict__ Bh, const f16* __restrict__ Bl,
    const float* __restrict__ bias, int Nbias,
    f16* __restrict__ Sh, float* __restrict__ part)
{
    int bn = blockIdx.x, bm = blockIdx.y;
    extern __shared__ __align__(16) char smem[];
    u32 sb = s2u(smem);
    int t = threadIdx.x, lane = t & 31, warp = t >> 5;
    int wm = warp & 1, wn = warp >> 1;

    float acc[4][4][4] = {};

    int nc = Ktot / 32;
    ldtile(sb + 0 * TB, Ah, bm * 128, KSTR, 0, t);
    ldtile(sb + 1 * TB, Bh, bn * 128, Ktot, 0, t);
    ldtile(sb + 2 * TB, Bl, bn * 128, Ktot, 0, t);
    asm volatile("cp.async.commit_group;");

    for (int c = 0; c < nc; c++) {
        if (c + 1 < nc) {
            u32 bb = sb + ((c + 1) & 1) * 3 * TB;
            int k0 = (c + 1) * 32;
            ldtile(bb + 0 * TB, Ah, bm * 128, KSTR, k0, t);
            ldtile(bb + 1 * TB, Bh, bn * 128, Ktot, k0, t);
            ldtile(bb + 2 * TB, Bl, bn * 128, Ktot, k0, t);
            asm volatile("cp.async.commit_group;");
            asm volatile("cp.async.wait_group 1;");
        } else {
            asm volatile("cp.async.wait_group 0;");
        }
        __syncthreads();
        u32 base = sb + (c & 1) * 3 * TB;
        u32 aH = base, bH = base + TB, bL = base + 2 * TB;
        #pragma unroll
        for (int kk = 0; kk < 32; kk += 16) {
            u32 AH[4][4], BH[4][2], BL[4][2];
            #pragma unroll
            for (int mt = 0; mt < 4; mt++) {
                u32 ro = (u32)((wm * 64 + mt * 16 + (lane & 15)) * 80 + (kk + (lane >> 4) * 8) * 2);
                ldsm4(AH[mt], aH + ro);
            }
            #pragma unroll
            for (int np = 0; np < 2; np++) {
                u32 ro = (u32)((wn * 32 + np * 16 + ((lane >> 4) * 8) + (lane & 7)) * 80
                               + (kk + ((lane >> 3) & 1) * 8) * 2);
                u32 r[4];
                ldsm4(r, bH + ro);
                BH[2 * np][0] = r[0]; BH[2 * np][1] = r[1];
                BH[2 * np + 1][0] = r[2]; BH[2 * np + 1][1] = r[3];
                ldsm4(r, bL + ro);
                BL[2 * np][0] = r[0]; BL[2 * np][1] = r[1];
                BL[2 * np + 1][0] = r[2]; BL[2 * np + 1][1] = r[3];
            }
            #pragma unroll
            for (int mt = 0; mt < 4; mt++)
                #pragma unroll
                for (int nt = 0; nt < 4; nt++) {
                    mma16816(acc[mt][nt], AH[mt], BH[nt]);
                    mma16816(acc[mt][nt], AH[mt], BL[nt]);
                }
        }
        __syncthreads();
    }

    if (Sh) {
        // write fp16 activations into next cat buffer
        #pragma unroll
        for (int mt = 0; mt < 4; mt++) {
            int rl0 = wm * 64 + mt * 16 + (lane >> 2);
            #pragma unroll
            for (int nt = 0; nt < 4; nt++) {
                int cl = wn * 32 + nt * 8 + (lane & 3) * 2;
                int col = bn * 128 + cl;
                float b0 = bias[col], b1 = bias[col + 1];
                #pragma unroll
                for (int h = 0; h < 2; h++) {
                    int row = bm * 128 + rl0 + h * 8;
                    float v0 = fmaxf(acc[mt][nt][2 * h + 0] + b0, 0.f);
                    float v1 = fmaxf(acc[mt][nt][2 * h + 1] + b1, 0.f);
                    __half2 p; p.x = __float2half_rn(v0); p.y = __float2half_rn(v1);
                    *(__half2*)(Sh + (size_t)row * KSTR + col) = p;
                }
            }
        }
    } else {
        // pool mode: per-column partial sums over this CTA's 128 rows
        float* sCol = (float*)smem;
        if (t < 128) sCol[t] = 0.f;
        __syncthreads();
        #pragma unroll
        for (int nt = 0; nt < 4; nt++) {
            int cl = wn * 32 + nt * 8 + (lane & 3) * 2;
            int col = bn * 128 + cl;
            float b0 = (col < Nbias) ? bias[col] : 0.f;
            float b1 = (col + 1 < Nbias) ? bias[col + 1] : 0.f;
            float p0 = 0.f, p1 = 0.f;
            #pragma unroll
            for (int mt = 0; mt < 4; mt++)
                #pragma unroll
                for (int h = 0; h < 2; h++) {
                    p0 += fmaxf(acc[mt][nt][2 * h + 0] + b0, 0.f);
                    p1 += fmaxf(acc[mt][nt][2 * h + 1] + b1, 0.f);
                }
            atomicAdd(&sCol[cl], p0);
            atomicAdd(&sCol[cl + 1], p1);
        }
        __syncthreads();
        if (t < 128) part[(size_t)(bm * 8 + bn) * 128 + t] = sCol[t];
    }
}

// ---------------- pool reduce: 4 row-tiles per batch ---------------------------
__global__ void reduce_pool(float* __restrict__ out) {
    int idx = blockIdx.x * 256 + threadIdx.x;
    if (idx >= BATCH * CLS) return;
    int b = idx / CLS, o = idx % CLS;
    int bn = o >> 7, c = o & 127;
    float s = 0.f;
    #pragma unroll
    for (int q = 0; q < 4; q++)
        s += g_part[(size_t)((b * 4 + q) * 8 + bn) * 128 + c];
    out[idx] = s * (1.0f / 512.0f);
}

// ---------------- launch --------------------------------------------------------
#define DIST_SMEM (128 * 136 * 2 * 2)   // 69632
#define SAGE_SMEM (6 * TB)              // 61440

extern "C" void kernel_launch(void* const* d_in, const int* in_sizes, int n_in,
                              void* d_out, int out_size) {
    const float* x   = (const float*)d_in[0];
    const float* wl0 = (const float*)d_in[1];
    const float* bl0 = (const float*)d_in[2];
    const float* wr0 = (const float*)d_in[3];
    const float* wl1 = (const float*)d_in[4];
    const float* bl1 = (const float*)d_in[5];
    const float* wr1 = (const float*)d_in[6];
    const float* wl2 = (const float*)d_in[7];
    const float* bl2 = (const float*)d_in[8];
    const float* wr2 = (const float*)d_in[9];
    float* out = (float*)d_out;

    f16 *c0h, *c1h, *w0h, *w0l, *w1h, *w1l, *w2h, *w2l;
    float* part;
    cudaGetSymbolAddress((void**)&c0h, g_c0h);
    cudaGetSymbolAddress((void**)&c1h, g_c1h);
    cudaGetSymbolAddress((void**)&w0h, g_w0h);
    cudaGetSymbolAddress((void**)&w0l, g_w0l);
    cudaGetSymbolAddress((void**)&w1h, g_w1h);
    cudaGetSymbolAddress((void**)&w1l, g_w1l);
    cudaGetSymbolAddress((void**)&w2h, g_w2h);
    cudaGetSymbolAddress((void**)&w2l, g_w2l);
    cudaGetSymbolAddress((void**)&part, g_part);

    cudaFuncSetAttribute(dist_half, cudaFuncAttributeMaxDynamicSharedMemorySize, DIST_SMEM);
    cudaFuncSetAttribute(sage_mma, cudaFuncAttributeMaxDynamicSharedMemorySize, SAGE_SMEM);

    sq_kernel<<<NN / 8, 256>>>(x);                                   // 1
    xprep_kernel<<<(NN * FEA / 4 + 255) / 256, 256>>>(x);            // 2
    wt_build01<<<dim3(512, 2), 256>>>(wl0, wr0, wl1, wr1);           // 3
    dist_half<<<2080, 256, DIST_SMEM>>>(c0h + 192);                  // 4 (profiled)
    wt_build2<<<(1024 * 512 + 255) / 256, 256>>>(wl2, wr2);          // 5
    topk_refine<<<NN, 256>>>(x);                                     // 6

    // layer 0: c0h = [agg(x) | x], K=384 -> h1 (fp16) into c1h self region
    gather_x<<<NN / 4, dim3(FEA / 4, 4)>>>(x, c0h);
    sage_mma<<<dim3(2, 64), 256, SAGE_SMEM>>>(c0h, 384, w0h, w0l, bl0, HID,
                                              c1h + 256, nullptr);
    // layer 1: c1h = [agg(h1) | h1], K=512 -> h2 into c0h self region
    gather_f16<<<NN / 8, dim3(32, 8)>>>(c1h + 256, c1h);
    sage_mma<<<dim3(2, 64), 256, SAGE_SMEM>>>(c1h, 512, w1h, w1l, bl1, HID,
                                              c0h + 256, nullptr);
    // layer 2: c0h = [agg(h2) | h2], K=512, N padded 1024 -> pool partials
    gather_f16<<<NN / 8, dim3(32, 8)>>>(c0h + 256, c0h);
    sage_mma<<<dim3(8, 64), 256, SAGE_SMEM>>>(c0h, 512, w2h, w2l, bl2, CLS,
                                              nullptr, part);

    reduce_pool<<<(BATCH * CLS + 255) / 256, 256>>>(out);
}

// round 8
// speedup vs baseline: 1.2028x; 1.0416x over previous
#include <cuda_runtime.h>
#include <cuda_fp16.h>
#include <cfloat>

#define NN   8192
#define FEA  192
#define HID  256
#define CLS  1000
#define KNB  9
#define NCAND 16
#define KSTR 512
#define BATCH 16

typedef unsigned int u32;
typedef unsigned short u16;
typedef unsigned long long u64;
typedef __half f16;

// ---------------- scratch ----------------------------------------------------
__device__ float g_sq[NN];
__device__ __half g_Dh[(long long)NN * NN];        // 128 MB approx distances
__device__ int   g_idx[NN * KNB];
__device__ f16   g_c0h[NN * KSTR];                 // cat buffer 0: [agg | self]
__device__ f16   g_c1h[NN * KSTR];                 // cat buffer 1
__device__ f16   g_w0h[256 * 384],  g_w0l[256 * 384];
__device__ f16   g_w1h[256 * 512],  g_w1l[256 * 512];
__device__ f16   g_w2h[1024 * 512], g_w2l[1024 * 512];
__device__ float g_part[1024 * 128];               // layer2 pool partials [bm*8+bn][128]

// ---------------- helpers ----------------------------------------------------
__device__ __forceinline__ u32 s2u(const void* p) {
    u32 a;
    asm("{.reg .u64 t; cvta.to.shared.u64 t, %1; cvt.u32.u64 %0, t;}" : "=r"(a) : "l"(p));
    return a;
}
__device__ __forceinline__ void cpa16(u32 dst, const void* src) {
    asm volatile("cp.async.cg.shared.global [%0], [%1], 16;" :: "r"(dst), "l"(src));
}
__device__ __forceinline__ void ldsm4(u32* r, u32 addr) {
    asm volatile("ldmatrix.sync.aligned.m8n8.x4.shared.b16 {%0,%1,%2,%3}, [%4];"
        : "=r"(r[0]), "=r"(r[1]), "=r"(r[2]), "=r"(r[3]) : "r"(addr));
}
__device__ __forceinline__ void mma16816(float* c, const u32* a, const u32* b) {
    asm volatile("mma.sync.aligned.m16n8k16.row.col.f32.f16.f16.f32 "
        "{%0,%1,%2,%3},{%4,%5,%6,%7},{%8,%9},{%0,%1,%2,%3};"
        : "+f"(c[0]), "+f"(c[1]), "+f"(c[2]), "+f"(c[3])
        : "r"(a[0]), "r"(a[1]), "r"(a[2]), "r"(a[3]), "r"(b[0]), "r"(b[1]));
}
__device__ __forceinline__ void spltw(float v, f16& h, f16& l) {
    h = __float2half_rn(v);
    l = __float2half_rn(v - __half2float(h));
}

// fp16 tile loader: [128 rows x 32 k] (row stride 40 halfs = 80B)
__device__ __forceinline__ void ldtile(u32 dstb, const f16* g, int row0, int ld, int k0, int t) {
    #pragma unroll
    for (int q = 0; q < 2; q++) {
        int id = t * 2 + q;
        int row = id >> 2, kq = id & 3;
        cpa16(dstb + row * 80 + kq * 16, g + (size_t)(row0 + row) * ld + k0 + kq * 8);
    }
}
// fp16 tile loader: [64 rows x 32 k]
__device__ __forceinline__ void ldtileA64(u32 dstb, const f16* g, int row0, int ld, int k0, int t) {
    int row = t >> 2, kq = t & 3;
    cpa16(dstb + row * 80 + kq * 16, g + (size_t)(row0 + row) * ld + k0 + kq * 8);
}

#define TB 10240     // 128-row fp16 tile: 128*40*2 bytes
#define ATB 5120     // 64-row fp16 tile
#define SSTG (ATB + 2 * TB)   // sage stage: A64 + Bh + Bl = 25600

// ---------------- small kernels ----------------------------------------------
__global__ void sq_kernel(const float* __restrict__ x) {
    int warp = (blockIdx.x * blockDim.x + threadIdx.x) >> 5;
    int lane = threadIdx.x & 31;
    if (warp >= NN) return;
    const float* r = x + (size_t)warp * FEA;
    float s = 0.f;
    for (int c = lane; c < FEA; c += 32) { float v = r[c]; s += v * v; }
    #pragma unroll
    for (int o = 16; o; o >>= 1) s += __shfl_xor_sync(0xffffffffu, s, o);
    if (lane == 0) g_sq[warp] = s;
}

__global__ void xprep_kernel(const float* __restrict__ x) {
    int g = blockIdx.x * 256 + threadIdx.x;
    if (g >= NN * FEA / 4) return;
    int r = g / 48, c4 = (g % 48) * 4;
    float4 v = *(const float4*)(x + (size_t)r * FEA + c4);
    __half2 p0; p0.x = __float2half_rn(v.x); p0.y = __float2half_rn(v.y);
    __half2 p1; p1.x = __float2half_rn(v.z); p1.y = __float2half_rn(v.w);
    size_t off = (size_t)r * KSTR + 192 + c4;
    *(__half2*)(g_c0h + off)     = p0;
    *(__half2*)(g_c0h + off + 2) = p1;
}

__global__ void wt_build01(const float* __restrict__ Wl0, const float* __restrict__ Wr0,
                           const float* __restrict__ Wl1, const float* __restrict__ Wr1) {
    int layer = blockIdx.y;
    const float* Wl = layer ? Wl1 : Wl0;
    const float* Wr = layer ? Wr1 : Wr0;
    f16* WTh = layer ? g_w1h : g_w0h;
    f16* WTl = layer ? g_w1l : g_w0l;
    int K1 = layer ? 256 : 192;
    int Ktot = 2 * K1;
    int total = 256 * Ktot;
    int idx = blockIdx.x * 256 + threadIdx.x;
    if (idx >= total) return;
    int k = idx % Ktot;
    int n = idx / Ktot;
    float v = (k < K1) ? Wl[(size_t)k * HID + n] : Wr[(size_t)(k - K1) * HID + n];
    f16 h, l; spltw(v, h, l);
    WTh[idx] = h; WTl[idx] = l;
}

__global__ void wt_build2(const float* __restrict__ Wl, const float* __restrict__ Wr) {
    int idx = blockIdx.x * 256 + threadIdx.x;
    if (idx >= 1024 * 512) return;
    int n = idx / 512, k = idx % 512;
    float v = 0.f;
    if (n < CLS) v = (k < 256) ? Wl[(size_t)k * CLS + n] : Wr[(size_t)(k - 256) * CLS + n];
    f16 h, l; spltw(v, h, l);
    g_w2h[idx] = h; g_w2l[idx] = l;
}

// ---------------- fp16 distance screen GEMM (triangular grid) -----------------
__global__ __launch_bounds__(256, 2) void dist_half(const f16* __restrict__ Xh) {
    int tp = blockIdx.x;
    int bj = (int)((sqrtf(8.f * tp + 1.f) - 1.f) * 0.5f);
    while ((bj + 1) * (bj + 2) / 2 <= tp) bj++;
    while (bj * (bj + 1) / 2 > tp) bj--;
    int bi = tp - bj * (bj + 1) / 2;

    extern __shared__ __align__(16) char smem[];
    u32 sb = s2u(smem);
    int t = threadIdx.x, lane = t & 31, warp = t >> 5;
    int wm = warp & 1, wn = warp >> 1;

    float acc[4][4][4] = {};

    const int NC = FEA / 32;   // 6
    ldtile(sb + 0 * TB, Xh, bi * 128, KSTR, 0, t);
    ldtile(sb + 1 * TB, Xh, bj * 128, KSTR, 0, t);
    asm volatile("cp.async.commit_group;");

    for (int c = 0; c < NC; c++) {
        if (c + 1 < NC) {
            u32 bb = sb + ((c + 1) & 1) * 2 * TB;
            int k0 = (c + 1) * 32;
            ldtile(bb + 0 * TB, Xh, bi * 128, KSTR, k0, t);
            ldtile(bb + 1 * TB, Xh, bj * 128, KSTR, k0, t);
            asm volatile("cp.async.commit_group;");
            asm volatile("cp.async.wait_group 1;");
        } else {
            asm volatile("cp.async.wait_group 0;");
        }
        __syncthreads();
        u32 base = sb + (c & 1) * 2 * TB;
        u32 aH = base, bH = base + TB;
        #pragma unroll
        for (int kk = 0; kk < 32; kk += 16) {
            u32 AH[4][4], BH[4][2];
            #pragma unroll
            for (int mt = 0; mt < 4; mt++) {
                u32 ro = (u32)((wm * 64 + mt * 16 + (lane & 15)) * 80 + (kk + (lane >> 4) * 8) * 2);
                ldsm4(AH[mt], aH + ro);
            }
            #pragma unroll
            for (int np = 0; np < 2; np++) {
                u32 ro = (u32)((wn * 32 + np * 16 + ((lane >> 4) * 8) + (lane & 7)) * 80
                               + (kk + ((lane >> 3) & 1) * 8) * 2);
                u32 r[4];
                ldsm4(r, bH + ro);
                BH[2 * np][0] = r[0]; BH[2 * np][1] = r[1];
                BH[2 * np + 1][0] = r[2]; BH[2 * np + 1][1] = r[3];
            }
            #pragma unroll
            for (int mt = 0; mt < 4; mt++)
                #pragma unroll
                for (int nt = 0; nt < 4; nt++)
                    mma16816(acc[mt][nt], AH[mt], BH[nt]);
        }
        __syncthreads();
    }

    // epilogue: stage both tiles as fp16 in smem, write coalesced
    u16* sD = (u16*)smem;            // [128][136]
    u16* sT = sD + 128 * 136;
    bool diag = (bi == bj);
    #pragma unroll
    for (int mt = 0; mt < 4; mt++) {
        int rl0 = wm * 64 + mt * 16 + (lane >> 2);
        #pragma unroll
        for (int nt = 0; nt < 4; nt++) {
            int cl = wn * 32 + nt * 8 + (lane & 3) * 2;
            float sqc0 = g_sq[bj * 128 + cl], sqc1 = g_sq[bj * 128 + cl + 1];
            #pragma unroll
            for (int h = 0; h < 2; h++) {
                int rl = rl0 + h * 8;
                float sr = g_sq[bi * 128 + rl];
                float d0 = sr + sqc0 - 2.f * acc[mt][nt][2 * h + 0];
                float d1 = sr + sqc1 - 2.f * acc[mt][nt][2 * h + 1];
                u16 b0 = __half_as_ushort(__float2half_rn(d0));
                u16 b1 = __half_as_ushort(__float2half_rn(d1));
                sD[rl * 136 + cl] = b0;
                sD[rl * 136 + cl + 1] = b1;
                if (!diag) {
                    sT[cl * 136 + rl] = b0;
                    sT[(cl + 1) * 136 + rl] = b1;
                }
            }
        }
    }
    __syncthreads();
    u16* gD = (u16*)g_Dh;
    for (int e = t; e < 128 * 16; e += 256) {
        int r = e >> 4, c8 = (e & 15) * 8;
        uint4 v = *(uint4*)&sD[r * 136 + c8];
        *(uint4*)(gD + (size_t)(bi * 128 + r) * NN + bj * 128 + c8) = v;
    }
    if (!diag) {
        for (int e = t; e < 128 * 16; e += 256) {
            int r = e >> 4, c8 = (e & 15) * 8;
            uint4 v = *(uint4*)&sT[r * 136 + c8];
            *(uint4*)(gD + (size_t)(bj * 128 + r) * NN + bi * 128 + c8) = v;
        }
    }
}

// ---------------- top-16 candidates + exact fp32 refine to top-9 --------------
__global__ __launch_bounds__(256) void topk_refine(const float* __restrict__ x) {
    int i = blockIdx.x;
    int t = threadIdx.x, lane = t & 31, wid = t >> 5;
    __shared__ u16 skey[NN];
    __shared__ u32 wmin[8];
    __shared__ u32 bcast;
    __shared__ int cand[NCAND];
    __shared__ float cdist[NCAND];
    __shared__ float xi[FEA];

    const u16* row = (const u16*)(g_Dh + (size_t)i * NN);
    int j0 = t * 32;
    u32 mylm = 0xFFFFFFFFu;
    #pragma unroll
    for (int q = 0; q < 4; q++) {
        uint4 v = __ldg((const uint4*)(row + j0 + q * 8));
        u32 w[4] = {v.x, v.y, v.z, v.w};
        #pragma unroll
        for (int p = 0; p < 4; p++) {
            #pragma unroll
            for (int hh = 0; hh < 2; hh++) {
                u16 hb = (u16)(w[p] >> (16 * hh));
                u16 key = (u16)(hb ^ ((hb & 0x8000) ? 0xFFFFu : 0x8000u));
                int j = j0 + q * 8 + p * 2 + hh;
                skey[j] = key;
                u32 pk = ((u32)key << 16) | (u32)j;
                mylm = min(mylm, pk);
            }
        }
    }

    for (int r = 0; r < NCAND; r++) {
        u32 v = mylm;
        #pragma unroll
        for (int o = 16; o; o >>= 1) v = min(v, __shfl_xor_sync(0xffffffffu, v, o));
        if (lane == 0) wmin[wid] = v;
        __syncthreads();
        if (t < 8) {
            u32 u = wmin[t];
            #pragma unroll
            for (int o = 4; o; o >>= 1) u = min(u, __shfl_xor_sync(0xffu, u, o));
            if (t == 0) { bcast = u; cand[r] = (int)(u & 0xFFFFu); }
        }
        __syncthreads();
        int jstar = (int)(bcast & 0xFFFFu);
        if ((jstar >> 5) == t) {
            skey[jstar] = 0xFFFFu;
            u32 nm = 0xFFFFFFFFu;
            #pragma unroll
            for (int q = 0; q < 32; q++) {
                int j = j0 + q;
                nm = min(nm, ((u32)skey[j] << 16) | (u32)j);
            }
            mylm = nm;
        }
        __syncthreads();
    }

    for (int d = t; d < FEA; d += 256) xi[d] = __ldg(x + (size_t)i * FEA + d);
    __syncthreads();
    #pragma unroll
    for (int q = 0; q < NCAND / 8; q++) {
        int c = wid + q * 8;
        int j = cand[c];
        const float* xj = x + (size_t)j * FEA;
        float s = 0.f;
        #pragma unroll
        for (int d = lane; d < FEA; d += 32) s = fmaf(xi[d], __ldg(xj + d), s);
        #pragma unroll
        for (int o = 16; o; o >>= 1) s += __shfl_xor_sync(0xffffffffu, s, o);
        if (lane == 0) cdist[c] = g_sq[i] + g_sq[j] - 2.f * s;
    }
    __syncthreads();
    if (t == 0) {
        u64 keys[NCAND];
        #pragma unroll
        for (int c = 0; c < NCAND; c++) {
            u32 b = __float_as_uint(cdist[c]);
            b ^= (b & 0x80000000u) ? 0xFFFFFFFFu : 0x80000000u;
            keys[c] = ((u64)b << 32) | (u32)cand[c];
        }
        #pragma unroll
        for (int r = 0; r < KNB; r++) {
            u64 best = keys[0]; int bs = 0;
            #pragma unroll
            for (int c = 1; c < NCAND; c++)
                if (keys[c] < best) { best = keys[c]; bs = c; }
            g_idx[i * KNB + r] = (int)(best & 0xFFFFFFFFull);
            keys[bs] = ~0ull;
        }
    }
}

// ---------------- gather + mean from fp32 x (layer 0) --------------------------
__global__ void gather_x(const float* __restrict__ x, f16* __restrict__ oh) {
    int row = blockIdx.x * 4 + threadIdx.y;
    int c4 = threadIdx.x * 4;
    const int* idp = g_idx + row * KNB;
    float4 s = make_float4(0.f, 0.f, 0.f, 0.f);
    #pragma unroll
    for (int j = 0; j < KNB; j++) {
        float4 v = __ldg((const float4*)(x + (size_t)idp[j] * FEA + c4));
        s.x += v.x; s.y += v.y; s.z += v.z; s.w += v.w;
    }
    const float inv = 1.0f / 9.0f;
    size_t off = (size_t)row * KSTR + c4;
    __half2 p0; p0.x = __float2half_rn(s.x * inv); p0.y = __float2half_rn(s.y * inv);
    __half2 p1; p1.x = __float2half_rn(s.z * inv); p1.y = __float2half_rn(s.w * inv);
    *(__half2*)(oh + off)     = p0;
    *(__half2*)(oh + off + 2) = p1;
}

// ---------------- gather + mean from fp16 cat self (layers 1,2) ----------------
__global__ void gather_f16(const f16* __restrict__ cat_self, f16* __restrict__ cat_agg) {
    int row = blockIdx.x * 8 + threadIdx.y;
    int c8 = threadIdx.x * 8;
    const int* idp = g_idx + row * KNB;
    float s[8] = {0.f, 0.f, 0.f, 0.f, 0.f, 0.f, 0.f, 0.f};
    #pragma unroll
    for (int j = 0; j < KNB; j++) {
        uint4 v = __ldg((const uint4*)(cat_self + (size_t)idp[j] * KSTR + c8));
        u32 w[4] = {v.x, v.y, v.z, v.w};
        #pragma unroll
        for (int p = 0; p < 4; p++) {
            float2 f = __half22float2(*(__half2*)&w[p]);
            s[2 * p] += f.x; s[2 * p + 1] += f.y;
        }
    }
    const float inv = 1.0f / 9.0f;
    u32 out[4];
    #pragma unroll
    for (int p = 0; p < 4; p++) {
        __half2 h; h.x = __float2half_rn(s[2 * p] * inv); h.y = __float2half_rn(s[2 * p + 1] * inv);
        out[p] = *(u32*)&h;
    }
    *(uint4*)(cat_agg + (size_t)row * KSTR + c8) = *(uint4*)out;
}

// ---------------- SAGE dual-GEMM, M64 tiles: relu(A@[Wl;Wr] + b) ----------------
// Sh != null: write fp16 to next cat buffer. part != null: pool partial sums.
__global__ __launch_bounds__(256, 2) void sage_mma(
    const f16* __restrict__ Ah, int Ktot,
    const f16* __restrict__ Bh, const f16* __restrict__ Bl,
    const float* __restrict__ bias, int Nbias,
    f16* __restrict__ Sh, float* __restrict__ part)
{
    int bn = blockIdx.x, bm = blockIdx.y;
    extern __shared__ __align__(16) char smem[];
    u32 sb = s2u(smem);
    int t = threadIdx.x, lane = t & 31, warp = t >> 5;
    int wm = warp & 1, wn = warp >> 1;

    float acc[2][4][4] = {};

    int nc = Ktot / 32;
    ldtileA64(sb + 0, Ah, bm * 64, KSTR, 0, t);
    ldtile(sb + ATB, Bh, bn * 128, Ktot, 0, t);
    ldtile(sb + ATB + TB, Bl, bn * 128, Ktot, 0, t);
    asm volatile("cp.async.commit_group;");

    for (int c = 0; c < nc; c++) {
        if (c + 1 < nc) {
            u32 bb = sb + ((c + 1) & 1) * SSTG;
            int k0 = (c + 1) * 32;
            ldtileA64(bb + 0, Ah, bm * 64, KSTR, k0, t);
            ldtile(bb + ATB, Bh, bn * 128, Ktot, k0, t);
            ldtile(bb + ATB + TB, Bl, bn * 128, Ktot, k0, t);
            asm volatile("cp.async.commit_group;");
            asm volatile("cp.async.wait_group 1;");
        } else {
            asm volatile("cp.async.wait_group 0;");
        }
        __syncthreads();
        u32 base = sb + (c & 1) * SSTG;
        u32 aH = base, bH = base + ATB, bL = base + ATB + TB;
        #pragma unroll
        for (int kk = 0; kk < 32; kk += 16) {
            u32 AH[2][4], BH[4][2], BL[4][2];
            #pragma unroll
            for (int mt = 0; mt < 2; mt++) {
                u32 ro = (u32)((wm * 32 + mt * 16 + (lane & 15)) * 80 + (kk + (lane >> 4) * 8) * 2);
                ldsm4(AH[mt], aH + ro);
            }
            #pragma unroll
            for (int np = 0; np < 2; np++) {
                u32 ro = (u32)((wn * 32 + np * 16 + ((lane >> 4) * 8) + (lane & 7)) * 80
                               + (kk + ((lane >> 3) & 1) * 8) * 2);
                u32 r[4];
                ldsm4(r, bH + ro);
                BH[2 * np][0] = r[0]; BH[2 * np][1] = r[1];
                BH[2 * np + 1][0] = r[2]; BH[2 * np + 1][1] = r[3];
                ldsm4(r, bL + ro);
                BL[2 * np][0] = r[0]; BL[2 * np][1] = r[1];
                BL[2 * np + 1][0] = r[2]; BL[2 * np + 1][1] = r[3];
            }
            #pragma unroll
            for (int mt = 0; mt < 2; mt++)
                #pragma unroll
                for (int nt = 0; nt < 4; nt++) {
                    mma16816(acc[mt][nt], AH[mt], BH[nt]);
                    mma16816(acc[mt][nt], AH[mt], BL[nt]);
                }
        }
        __syncthreads();
    }

    if (Sh) {
        #pragma unroll
        for (int mt = 0; mt < 2; mt++) {
            int rl0 = wm * 32 + mt * 16 + (lane >> 2);
            #pragma unroll
            for (int nt = 0; nt < 4; nt++) {
                int cl = wn * 32 + nt * 8 + (lane & 3) * 2;
                int col = bn * 128 + cl;
                float b0 = bias[col], b1 = bias[col + 1];
                #pragma unroll
                for (int h = 0; h < 2; h++) {
                    int row = bm * 64 + rl0 + h * 8;
                    float v0 = fmaxf(acc[mt][nt][2 * h + 0] + b0, 0.f);
                    float v1 = fmaxf(acc[mt][nt][2 * h + 1] + b1, 0.f);
                    __half2 p; p.x = __float2half_rn(v0); p.y = __float2half_rn(v1);
                    *(__half2*)(Sh + (size_t)row * KSTR + col) = p;
                }
            }
        }
    } else {
        float* sCol = (float*)smem;
        if (t < 128) sCol[t] = 0.f;
        __syncthreads();
        #pragma unroll
        for (int nt = 0; nt < 4; nt++) {
            int cl = wn * 32 + nt * 8 + (lane & 3) * 2;
            int col = bn * 128 + cl;
            float b0 = (col < Nbias) ? bias[col] : 0.f;
            float b1 = (col + 1 < Nbias) ? bias[col + 1] : 0.f;
            float p0 = 0.f, p1 = 0.f;
            #pragma unroll
            for (int mt = 0; mt < 2; mt++)
                #pragma unroll
                for (int h = 0; h < 2; h++) {
                    p0 += fmaxf(acc[mt][nt][2 * h + 0] + b0, 0.f);
                    p1 += fmaxf(acc[mt][nt][2 * h + 1] + b1, 0.f);
                }
            atomicAdd(&sCol[cl], p0);
            atomicAdd(&sCol[cl + 1], p1);
        }
        __syncthreads();
        if (t < 128) part[(size_t)(bm * 8 + bn) * 128 + t] = sCol[t];
    }
}

// ---------------- pool reduce: 8 row-tiles (64 rows each) per batch -------------
__global__ void reduce_pool(float* __restrict__ out) {
    int idx = blockIdx.x * 256 + threadIdx.x;
    if (idx >= BATCH * CLS) return;
    int b = idx / CLS, o = idx % CLS;
    int bn = o >> 7, c = o & 127;
    float s = 0.f;
    #pragma unroll
    for (int q = 0; q < 8; q++)
        s += g_part[(size_t)((b * 8 + q) * 8 + bn) * 128 + c];
    out[idx] = s * (1.0f / 512.0f);
}

// ---------------- launch --------------------------------------------------------
#define DIST_SMEM (128 * 136 * 2 * 2)   // 69632
#define SAGE_SMEM (2 * SSTG)            // 51200

extern "C" void kernel_launch(void* const* d_in, const int* in_sizes, int n_in,
                              void* d_out, int out_size) {
    const float* x   = (const float*)d_in[0];
    const float* wl0 = (const float*)d_in[1];
    const float* bl0 = (const float*)d_in[2];
    const float* wr0 = (const float*)d_in[3];
    const float* wl1 = (const float*)d_in[4];
    const float* bl1 = (const float*)d_in[5];
    const float* wr1 = (const float*)d_in[6];
    const float* wl2 = (const float*)d_in[7];
    const float* bl2 = (const float*)d_in[8];
    const float* wr2 = (const float*)d_in[9];
    float* out = (float*)d_out;

    f16 *c0h, *c1h, *w0h, *w0l, *w1h, *w1l, *w2h, *w2l;
    float* part;
    cudaGetSymbolAddress((void**)&c0h, g_c0h);
    cudaGetSymbolAddress((void**)&c1h, g_c1h);
    cudaGetSymbolAddress((void**)&w0h, g_w0h);
    cudaGetSymbolAddress((void**)&w0l, g_w0l);
    cudaGetSymbolAddress((void**)&w1h, g_w1h);
    cudaGetSymbolAddress((void**)&w1l, g_w1l);
    cudaGetSymbolAddress((void**)&w2h, g_w2h);
    cudaGetSymbolAddress((void**)&w2l, g_w2l);
    cudaGetSymbolAddress((void**)&part, g_part);

    cudaFuncSetAttribute(dist_half, cudaFuncAttributeMaxDynamicSharedMemorySize, DIST_SMEM);
    cudaFuncSetAttribute(sage_mma, cudaFuncAttributeMaxDynamicSharedMemorySize, SAGE_SMEM);

    sq_kernel<<<NN / 8, 256>>>(x);                                   // 1
    xprep_kernel<<<(NN * FEA / 4 + 255) / 256, 256>>>(x);            // 2
    wt_build01<<<dim3(512, 2), 256>>>(wl0, wr0, wl1, wr1);           // 3
    dist_half<<<2080, 256, DIST_SMEM>>>(c0h + 192);                  // 4 (profiled)
    wt_build2<<<(1024 * 512 + 255) / 256, 256>>>(wl2, wr2);          // 5
    topk_refine<<<NN, 256>>>(x);                                     // 6

    // layer 0: c0h = [agg(x) | x], K=384 -> h1 (fp16) into c1h self region
    gather_x<<<NN / 4, dim3(FEA / 4, 4)>>>(x, c0h);
    sage_mma<<<dim3(2, 128), 256, SAGE_SMEM>>>(c0h, 384, w0h, w0l, bl0, HID,
                                               c1h + 256, nullptr);
    // layer 1: c1h = [agg(h1) | h1], K=512 -> h2 into c0h self region
    gather_f16<<<NN / 8, dim3(32, 8)>>>(c1h + 256, c1h);
    sage_mma<<<dim3(2, 128), 256, SAGE_SMEM>>>(c1h, 512, w1h, w1l, bl1, HID,
                                               c0h + 256, nullptr);
    // layer 2: c0h = [agg(h2) | h2], K=512, N padded 1024 -> pool partials
    gather_f16<<<NN / 8, dim3(32, 8)>>>(c0h + 256, c0h);
    sage_mma<<<dim3(8, 128), 256, SAGE_SMEM>>>(c0h, 512, w2h, w2l, bl2, CLS,
                                               nullptr, part);

    reduce_pool<<<(BATCH * CLS + 255) / 256, 256>>>(out);
}

// round 9
// speedup vs baseline: 1.2449x; 1.0351x over previous
#include <cuda_runtime.h>
#include <cuda_fp16.h>
#include <cfloat>

#define NN   8192
#define FEA  192
#define HID  256
#define CLS  1000
#define KNB  9
#define NCAND 16
#define KSTR 512
#define BATCH 16

typedef unsigned int u32;
typedef unsigned short u16;
typedef unsigned long long u64;
typedef __half f16;

// ---------------- scratch ----------------------------------------------------
__device__ float g_sq[NN];
__device__ __half g_Dh[(long long)NN * NN];        // 128 MB approx distances
__device__ int   g_idx[NN * KNB];
__device__ f16   g_c0h[NN * KSTR];                 // cat buffer 0: [agg | self]
__device__ f16   g_c1h[NN * KSTR];                 // cat buffer 1
__device__ f16   g_w0h[256 * 384],  g_w0l[256 * 384];
__device__ f16   g_w1h[256 * 512],  g_w1l[256 * 512];
__device__ f16   g_w2h[1024 * 512], g_w2l[1024 * 512];
__device__ float g_part[1024 * 128];               // layer2 pool partials

// ---------------- helpers ----------------------------------------------------
__device__ __forceinline__ u32 s2u(const void* p) {
    u32 a;
    asm("{.reg .u64 t; cvta.to.shared.u64 t, %1; cvt.u32.u64 %0, t;}" : "=r"(a) : "l"(p));
    return a;
}
__device__ __forceinline__ void cpa16(u32 dst, const void* src) {
    asm volatile("cp.async.cg.shared.global [%0], [%1], 16;" :: "r"(dst), "l"(src));
}
__device__ __forceinline__ void ldsm4(u32* r, u32 addr) {
    asm volatile("ldmatrix.sync.aligned.m8n8.x4.shared.b16 {%0,%1,%2,%3}, [%4];"
        : "=r"(r[0]), "=r"(r[1]), "=r"(r[2]), "=r"(r[3]) : "r"(addr));
}
__device__ __forceinline__ void mma16816(float* c, const u32* a, const u32* b) {
    asm volatile("mma.sync.aligned.m16n8k16.row.col.f32.f16.f16.f32 "
        "{%0,%1,%2,%3},{%4,%5,%6,%7},{%8,%9},{%0,%1,%2,%3};"
        : "+f"(c[0]), "+f"(c[1]), "+f"(c[2]), "+f"(c[3])
        : "r"(a[0]), "r"(a[1]), "r"(a[2]), "r"(a[3]), "r"(b[0]), "r"(b[1]));
}
__device__ __forceinline__ void spltw(float v, f16& h, f16& l) {
    h = __float2half_rn(v);
    l = __float2half_rn(v - __half2float(h));
}

// fp16 tile loader: [128 rows x 32 k] (row stride 40 halfs = 80B)
__device__ __forceinline__ void ldtile(u32 dstb, const f16* g, int row0, int ld, int k0, int t) {
    #pragma unroll
    for (int q = 0; q < 2; q++) {
        int id = t * 2 + q;
        int row = id >> 2, kq = id & 3;
        cpa16(dstb + row * 80 + kq * 16, g + (size_t)(row0 + row) * ld + k0 + kq * 8);
    }
}
// fp16 tile loader: [64 rows x 32 k]
__device__ __forceinline__ void ldtileA64(u32 dstb, const f16* g, int row0, int ld, int k0, int t) {
    int row = t >> 2, kq = t & 3;
    cpa16(dstb + row * 80 + kq * 16, g + (size_t)(row0 + row) * ld + k0 + kq * 8);
}

#define TB 10240     // 128-row fp16 tile
#define ATB 5120     // 64-row fp16 tile
#define SSTG (ATB + 2 * TB)   // sage stage = 25600

// ---------------- small kernels ----------------------------------------------
__global__ void sq_kernel(const float* __restrict__ x) {
    int warp = (blockIdx.x * blockDim.x + threadIdx.x) >> 5;
    int lane = threadIdx.x & 31;
    if (warp >= NN) return;
    const float* r = x + (size_t)warp * FEA;
    float s = 0.f;
    for (int c = lane; c < FEA; c += 32) { float v = r[c]; s += v * v; }
    #pragma unroll
    for (int o = 16; o; o >>= 1) s += __shfl_xor_sync(0xffffffffu, s, o);
    if (lane == 0) g_sq[warp] = s;
}

__global__ void xprep_kernel(const float* __restrict__ x) {
    int g = blockIdx.x * 256 + threadIdx.x;
    if (g >= NN * FEA / 4) return;
    int r = g / 48, c4 = (g % 48) * 4;
    float4 v = *(const float4*)(x + (size_t)r * FEA + c4);
    __half2 p0; p0.x = __float2half_rn(v.x); p0.y = __float2half_rn(v.y);
    __half2 p1; p1.x = __float2half_rn(v.z); p1.y = __float2half_rn(v.w);
    size_t off = (size_t)r * KSTR + 192 + c4;
    *(__half2*)(g_c0h + off)     = p0;
    *(__half2*)(g_c0h + off + 2) = p1;
}

__global__ void wt_build01(const float* __restrict__ Wl0, const float* __restrict__ Wr0,
                           const float* __restrict__ Wl1, const float* __restrict__ Wr1) {
    int layer = blockIdx.y;
    const float* Wl = layer ? Wl1 : Wl0;
    const float* Wr = layer ? Wr1 : Wr0;
    f16* WTh = layer ? g_w1h : g_w0h;
    f16* WTl = layer ? g_w1l : g_w0l;
    int K1 = layer ? 256 : 192;
    int Ktot = 2 * K1;
    int total = 256 * Ktot;
    int idx = blockIdx.x * 256 + threadIdx.x;
    if (idx >= total) return;
    int k = idx % Ktot;
    int n = idx / Ktot;
    float v = (k < K1) ? Wl[(size_t)k * HID + n] : Wr[(size_t)(k - K1) * HID + n];
    f16 h, l; spltw(v, h, l);
    WTh[idx] = h; WTl[idx] = l;
}

__global__ void wt_build2(const float* __restrict__ Wl, const float* __restrict__ Wr) {
    int idx = blockIdx.x * 256 + threadIdx.x;
    if (idx >= 1024 * 512) return;
    int n = idx / 512, k = idx % 512;
    float v = 0.f;
    if (n < CLS) v = (k < 256) ? Wl[(size_t)k * CLS + n] : Wr[(size_t)(k - 256) * CLS + n];
    f16 h, l; spltw(v, h, l);
    g_w2h[idx] = h; g_w2l[idx] = l;
}

// ---------------- fp16 distance screen GEMM (triangular grid) -----------------
__global__ __launch_bounds__(256, 2) void dist_half(const f16* __restrict__ Xh) {
    int tp = blockIdx.x;
    int bj = (int)((sqrtf(8.f * tp + 1.f) - 1.f) * 0.5f);
    while ((bj + 1) * (bj + 2) / 2 <= tp) bj++;
    while (bj * (bj + 1) / 2 > tp) bj--;
    int bi = tp - bj * (bj + 1) / 2;

    extern __shared__ __align__(16) char smem[];
    u32 sb = s2u(smem);
    int t = threadIdx.x, lane = t & 31, warp = t >> 5;
    int wm = warp & 1, wn = warp >> 1;

    float acc[4][4][4] = {};

    const int NC = FEA / 32;   // 6
    ldtile(sb + 0 * TB, Xh, bi * 128, KSTR, 0, t);
    ldtile(sb + 1 * TB, Xh, bj * 128, KSTR, 0, t);
    asm volatile("cp.async.commit_group;");

    for (int c = 0; c < NC; c++) {
        if (c + 1 < NC) {
            u32 bb = sb + ((c + 1) & 1) * 2 * TB;
            int k0 = (c + 1) * 32;
            ldtile(bb + 0 * TB, Xh, bi * 128, KSTR, k0, t);
            ldtile(bb + 1 * TB, Xh, bj * 128, KSTR, k0, t);
            asm volatile("cp.async.commit_group;");
            asm volatile("cp.async.wait_group 1;");
        } else {
            asm volatile("cp.async.wait_group 0;");
        }
        __syncthreads();
        u32 base = sb + (c & 1) * 2 * TB;
        u32 aH = base, bH = base + TB;
        #pragma unroll
        for (int kk = 0; kk < 32; kk += 16) {
            u32 AH[4][4], BH[4][2];
            #pragma unroll
            for (int mt = 0; mt < 4; mt++) {
                u32 ro = (u32)((wm * 64 + mt * 16 + (lane & 15)) * 80 + (kk + (lane >> 4) * 8) * 2);
                ldsm4(AH[mt], aH + ro);
            }
            #pragma unroll
            for (int np = 0; np < 2; np++) {
                u32 ro = (u32)((wn * 32 + np * 16 + ((lane >> 4) * 8) + (lane & 7)) * 80
                               + (kk + ((lane >> 3) & 1) * 8) * 2);
                u32 r[4];
                ldsm4(r, bH + ro);
                BH[2 * np][0] = r[0]; BH[2 * np][1] = r[1];
                BH[2 * np + 1][0] = r[2]; BH[2 * np + 1][1] = r[3];
            }
            #pragma unroll
            for (int mt = 0; mt < 4; mt++)
                #pragma unroll
                for (int nt = 0; nt < 4; nt++)
                    mma16816(acc[mt][nt], AH[mt], BH[nt]);
        }
        __syncthreads();
    }

    u16* sD = (u16*)smem;            // [128][136]
    u16* sT = sD + 128 * 136;
    bool diag = (bi == bj);
    #pragma unroll
    for (int mt = 0; mt < 4; mt++) {
        int rl0 = wm * 64 + mt * 16 + (lane >> 2);
        #pragma unroll
        for (int nt = 0; nt < 4; nt++) {
            int cl = wn * 32 + nt * 8 + (lane & 3) * 2;
            float sqc0 = g_sq[bj * 128 + cl], sqc1 = g_sq[bj * 128 + cl + 1];
            #pragma unroll
            for (int h = 0; h < 2; h++) {
                int rl = rl0 + h * 8;
                float sr = g_sq[bi * 128 + rl];
                float d0 = sr + sqc0 - 2.f * acc[mt][nt][2 * h + 0];
                float d1 = sr + sqc1 - 2.f * acc[mt][nt][2 * h + 1];
                u16 b0 = __half_as_ushort(__float2half_rn(d0));
                u16 b1 = __half_as_ushort(__float2half_rn(d1));
                sD[rl * 136 + cl] = b0;
                sD[rl * 136 + cl + 1] = b1;
                if (!diag) {
                    sT[cl * 136 + rl] = b0;
                    sT[(cl + 1) * 136 + rl] = b1;
                }
            }
        }
    }
    __syncthreads();
    u16* gD = (u16*)g_Dh;
    for (int e = t; e < 128 * 16; e += 256) {
        int r = e >> 4, c8 = (e & 15) * 8;
        uint4 v = *(uint4*)&sD[r * 136 + c8];
        *(uint4*)(gD + (size_t)(bi * 128 + r) * NN + bj * 128 + c8) = v;
    }
    if (!diag) {
        for (int e = t; e < 128 * 16; e += 256) {
            int r = e >> 4, c8 = (e & 15) * 8;
            uint4 v = *(uint4*)&sT[r * 136 + c8];
            *(uint4*)(gD + (size_t)(bj * 128 + r) * NN + bi * 128 + c8) = v;
        }
    }
}

// ---------------- top-16 candidates + exact fp32 refine to top-9 --------------
__global__ __launch_bounds__(256) void topk_refine(const float* __restrict__ x) {
    int i = blockIdx.x;
    int t = threadIdx.x, lane = t & 31, wid = t >> 5;
    __shared__ u16 skey[NN];
    __shared__ u32 wmin[8];
    __shared__ u32 bcast;
    __shared__ int cand[NCAND];
    __shared__ float cdist[NCAND];
    __shared__ float xi[FEA];

    const u16* row = (const u16*)(g_Dh + (size_t)i * NN);
    int j0 = t * 32;
    u32 mylm = 0xFFFFFFFFu;
    #pragma unroll
    for (int q = 0; q < 4; q++) {
        uint4 v = __ldg((const uint4*)(row + j0 + q * 8));
        u32 w[4] = {v.x, v.y, v.z, v.w};
        #pragma unroll
        for (int p = 0; p < 4; p++) {
            #pragma unroll
            for (int hh = 0; hh < 2; hh++) {
                u16 hb = (u16)(w[p] >> (16 * hh));
                u16 key = (u16)(hb ^ ((hb & 0x8000) ? 0xFFFFu : 0x8000u));
                int j = j0 + q * 8 + p * 2 + hh;
                skey[j] = key;
                u32 pk = ((u32)key << 16) | (u32)j;
                mylm = min(mylm, pk);
            }
        }
    }

    for (int r = 0; r < NCAND; r++) {
        u32 v = mylm;
        #pragma unroll
        for (int o = 16; o; o >>= 1) v = min(v, __shfl_xor_sync(0xffffffffu, v, o));
        if (lane == 0) wmin[wid] = v;
        __syncthreads();
        if (t < 8) {
            u32 u = wmin[t];
            #pragma unroll
            for (int o = 4; o; o >>= 1) u = min(u, __shfl_xor_sync(0xffu, u, o));
            if (t == 0) { bcast = u; cand[r] = (int)(u & 0xFFFFu); }
        }
        __syncthreads();
        int jstar = (int)(bcast & 0xFFFFu);
        if ((jstar >> 5) == t) {
            skey[jstar] = 0xFFFFu;
            u32 nm = 0xFFFFFFFFu;
            #pragma unroll
            for (int q = 0; q < 32; q++) {
                int j = j0 + q;
                nm = min(nm, ((u32)skey[j] << 16) | (u32)j);
            }
            mylm = nm;
        }
        __syncthreads();
    }

    for (int d = t; d < FEA; d += 256) xi[d] = __ldg(x + (size_t)i * FEA + d);
    __syncthreads();
    #pragma unroll
    for (int q = 0; q < NCAND / 8; q++) {
        int c = wid + q * 8;
        int j = cand[c];
        const float* xj = x + (size_t)j * FEA;
        float s = 0.f;
        #pragma unroll
        for (int d = lane; d < FEA; d += 32) s = fmaf(xi[d], __ldg(xj + d), s);
        #pragma unroll
        for (int o = 16; o; o >>= 1) s += __shfl_xor_sync(0xffffffffu, s, o);
        if (lane == 0) cdist[c] = g_sq[i] + g_sq[j] - 2.f * s;
    }
    __syncthreads();
    if (t == 0) {
        u64 keys[NCAND];
        #pragma unroll
        for (int c = 0; c < NCAND; c++) {
            u32 b = __float_as_uint(cdist[c]);
            b ^= (b & 0x80000000u) ? 0xFFFFFFFFu : 0x80000000u;
            keys[c] = ((u64)b << 32) | (u32)cand[c];
        }
        #pragma unroll
        for (int r = 0; r < KNB; r++) {
            u64 best = keys[0]; int bs = 0;
            #pragma unroll
            for (int c = 1; c < NCAND; c++)
                if (keys[c] < best) { best = keys[c]; bs = c; }
            g_idx[i * KNB + r] = (int)(best & 0xFFFFFFFFull);
            keys[bs] = ~0ull;
        }
    }
}

// ---------------- gather + mean from fp32 x (layer 0) --------------------------
__global__ void gather_x(const float* __restrict__ x, f16* __restrict__ oh) {
    int row = blockIdx.x * 4 + threadIdx.y;
    int c4 = threadIdx.x * 4;
    const int* idp = g_idx + row * KNB;
    float4 s = make_float4(0.f, 0.f, 0.f, 0.f);
    #pragma unroll
    for (int j = 0; j < KNB; j++) {
        float4 v = __ldg((const float4*)(x + (size_t)idp[j] * FEA + c4));
        s.x += v.x; s.y += v.y; s.z += v.z; s.w += v.w;
    }
    const float inv = 1.0f / 9.0f;
    size_t off = (size_t)row * KSTR + c4;
    __half2 p0; p0.x = __float2half_rn(s.x * inv); p0.y = __float2half_rn(s.y * inv);
    __half2 p1; p1.x = __float2half_rn(s.z * inv); p1.y = __float2half_rn(s.w * inv);
    *(__half2*)(oh + off)     = p0;
    *(__half2*)(oh + off + 2) = p1;
}

// ---------------- gather + mean from fp16 cat self (layers 1,2) ----------------
__global__ void gather_f16(const f16* __restrict__ cat_self, f16* __restrict__ cat_agg) {
    int row = blockIdx.x * 8 + threadIdx.y;
    int c8 = threadIdx.x * 8;
    const int* idp = g_idx + row * KNB;
    float s[8] = {0.f, 0.f, 0.f, 0.f, 0.f, 0.f, 0.f, 0.f};
    #pragma unroll
    for (int j = 0; j < KNB; j++) {
        uint4 v = __ldg((const uint4*)(cat_self + (size_t)idp[j] * KSTR + c8));
        u32 w[4] = {v.x, v.y, v.z, v.w};
        #pragma unroll
        for (int p = 0; p < 4; p++) {
            float2 f = __half22float2(*(__half2*)&w[p]);
            s[2 * p] += f.x; s[2 * p + 1] += f.y;
        }
    }
    const float inv = 1.0f / 9.0f;
    u32 out[4];
    #pragma unroll
    for (int p = 0; p < 4; p++) {
        __half2 h; h.x = __float2half_rn(s[2 * p] * inv); h.y = __float2half_rn(s[2 * p + 1] * inv);
        out[p] = *(u32*)&h;
    }
    *(uint4*)(cat_agg + (size_t)row * KSTR + c8) = *(uint4*)out;
}

// ---------------- SAGE dual-GEMM, M64 tiles, 3 CTAs/SM --------------------------
__global__ __launch_bounds__(256, 3) void sage_mma(
    const f16* __restrict__ Ah, int Ktot,
    const f16* __restrict__ Bh, const f16* __restrict__ Bl,
    const float* __restrict__ bias, int Nbias,
    f16* __restrict__ Sh, float* __restrict__ part)
{
    int bn = blockIdx.x, bm = blockIdx.y;
    extern __shared__ __align__(16) char smem[];
    u32 sb = s2u(smem);
    int t = threadIdx.x, lane = t & 31, warp = t >> 5;
    int wm = warp & 1, wn = warp >> 1;

    float acc[2][4][4] = {};

    int nc = Ktot / 32;
    ldtileA64(sb + 0, Ah, bm * 64, KSTR, 0, t);
    ldtile(sb + ATB, Bh, bn * 128, Ktot, 0, t);
    ldtile(sb + ATB + TB, Bl, bn * 128, Ktot, 0, t);
    asm volatile("cp.async.commit_group;");

    for (int c = 0; c < nc; c++) {
        if (c + 1 < nc) {
            u32 bb = sb + ((c + 1) & 1) * SSTG;
            int k0 = (c + 1) * 32;
            ldtileA64(bb + 0, Ah, bm * 64, KSTR, k0, t);
            ldtile(bb + ATB, Bh, bn * 128, Ktot, k0, t);
            ldtile(bb + ATB + TB, Bl, bn * 128, Ktot, k0, t);
            asm volatile("cp.async.commit_group;");
            asm volatile("cp.async.wait_group 1;");
        } else {
            asm volatile("cp.async.wait_group 0;");
        }
        __syncthreads();
        u32 base = sb + (c & 1) * SSTG;
        u32 aH = base, bH = base + ATB, bL = base + ATB + TB;
        #pragma unroll
        for (int kk = 0; kk < 32; kk += 16) {
            u32 AH[2][4], BH[4][2], BL[4][2];
            #pragma unroll
            for (int mt = 0; mt < 2; mt++) {
                u32 ro = (u32)((wm * 32 + mt * 16 + (lane & 15)) * 80 + (kk + (lane >> 4) * 8) * 2);
                ldsm4(AH[mt], aH + ro);
            }
            #pragma unroll
            for (int np = 0; np < 2; np++) {
                u32 ro = (u32)((wn * 32 + np * 16 + ((lane >> 4) * 8) + (lane & 7)) * 80
                               + (kk + ((lane >> 3) & 1) * 8) * 2);
                u32 r[4];
                ldsm4(r, bH + ro);
                BH[2 * np][0] = r[0]; BH[2 * np][1] = r[1];
                BH[2 * np + 1][0] = r[2]; BH[2 * np + 1][1] = r[3];
                ldsm4(r, bL + ro);
                BL[2 * np][0] = r[0]; BL[2 * np][1] = r[1];
                BL[2 * np + 1][0] = r[2]; BL[2 * np + 1][1] = r[3];
            }
            #pragma unroll
            for (int mt = 0; mt < 2; mt++)
                #pragma unroll
                for (int nt = 0; nt < 4; nt++) {
                    mma16816(acc[mt][nt], AH[mt], BH[nt]);
                    mma16816(acc[mt][nt], AH[mt], BL[nt]);
                }
        }
        __syncthreads();
    }

    if (Sh) {
        #pragma unroll
        for (int mt = 0; mt < 2; mt++) {
            int rl0 = wm * 32 + mt * 16 + (lane >> 2);
            #pragma unroll
            for (int nt = 0; nt < 4; nt++) {
                int cl = wn * 32 + nt * 8 + (lane & 3) * 2;
                int col = bn * 128 + cl;
                float b0 = bias[col], b1 = bias[col + 1];
                #pragma unroll
                for (int h = 0; h < 2; h++) {
                    int row = bm * 64 + rl0 + h * 8;
                    float v0 = fmaxf(acc[mt][nt][2 * h + 0] + b0, 0.f);
                    float v1 = fmaxf(acc[mt][nt][2 * h + 1] + b1, 0.f);
                    __half2 p; p.x = __float2half_rn(v0); p.y = __float2half_rn(v1);
                    *(__half2*)(Sh + (size_t)row * KSTR + col) = p;
                }
            }
        }
    } else {
        float* sCol = (float*)smem;
        if (t < 128) sCol[t] = 0.f;
        __syncthreads();
        #pragma unroll
        for (int nt = 0; nt < 4; nt++) {
            int cl = wn * 32 + nt * 8 + (lane & 3) * 2;
            int col = bn * 128 + cl;
            float b0 = (col < Nbias) ? bias[col] : 0.f;
            float b1 = (col + 1 < Nbias) ? bias[col + 1] : 0.f;
            float p0 = 0.f, p1 = 0.f;
            #pragma unroll
            for (int mt = 0; mt < 2; mt++)
                #pragma unroll
                for (int h = 0; h < 2; h++) {
                    p0 += fmaxf(acc[mt][nt][2 * h + 0] + b0, 0.f);
                    p1 += fmaxf(acc[mt][nt][2 * h + 1] + b1, 0.f);
                }
            atomicAdd(&sCol[cl], p0);
            atomicAdd(&sCol[cl + 1], p1);
        }
        __syncthreads();
        if (t < 128) part[(size_t)(bm * 8 + bn) * 128 + t] = sCol[t];
    }
}

// ---------------- pool reduce ----------------------------------------------------
__global__ void reduce_pool(float* __restrict__ out) {
    int idx = blockIdx.x * 256 + threadIdx.x;
    if (idx >= BATCH * CLS) return;
    int b = idx / CLS, o = idx % CLS;
    int bn = o >> 7, c = o & 127;
    float s = 0.f;
    #pragma unroll
    for (int q = 0; q < 8; q++)
        s += g_part[(size_t)((b * 8 + q) * 8 + bn) * 128 + c];
    out[idx] = s * (1.0f / 512.0f);
}

// ---------------- launch --------------------------------------------------------
#define DIST_SMEM (128 * 136 * 2 * 2)   // 69632
#define SAGE_SMEM (2 * SSTG)            // 51200

extern "C" void kernel_launch(void* const* d_in, const int* in_sizes, int n_in,
                              void* d_out, int out_size) {
    const float* x   = (const float*)d_in[0];
    const float* wl0 = (const float*)d_in[1];
    const float* bl0 = (const float*)d_in[2];
    const float* wr0 = (const float*)d_in[3];
    const float* wl1 = (const float*)d_in[4];
    const float* bl1 = (const float*)d_in[5];
    const float* wr1 = (const float*)d_in[6];
    const float* wl2 = (const float*)d_in[7];
    const float* bl2 = (const float*)d_in[8];
    const float* wr2 = (const float*)d_in[9];
    float* out = (float*)d_out;

    f16 *c0h, *c1h, *w0h, *w0l, *w1h, *w1l, *w2h, *w2l;
    float* part;
    cudaGetSymbolAddress((void**)&c0h, g_c0h);
    cudaGetSymbolAddress((void**)&c1h, g_c1h);
    cudaGetSymbolAddress((void**)&w0h, g_w0h);
    cudaGetSymbolAddress((void**)&w0l, g_w0l);
    cudaGetSymbolAddress((void**)&w1h, g_w1h);
    cudaGetSymbolAddress((void**)&w1l, g_w1l);
    cudaGetSymbolAddress((void**)&w2h, g_w2h);
    cudaGetSymbolAddress((void**)&w2l, g_w2l);
    cudaGetSymbolAddress((void**)&part, g_part);

    cudaFuncSetAttribute(dist_half, cudaFuncAttributeMaxDynamicSharedMemorySize, DIST_SMEM);
    cudaFuncSetAttribute(sage_mma, cudaFuncAttributeMaxDynamicSharedMemorySize, SAGE_SMEM);

    sq_kernel<<<NN / 8, 256>>>(x);                                   // 1
    xprep_kernel<<<(NN * FEA / 4 + 255) / 256, 256>>>(x);            // 2
    dist_half<<<2080, 256, DIST_SMEM>>>(c0h + 192);                  // 3
    topk_refine<<<NN, 256>>>(x);                                     // 4 (profiled)
    wt_build01<<<dim3(512, 2), 256>>>(wl0, wr0, wl1, wr1);           // 5
    wt_build2<<<(1024 * 512 + 255) / 256, 256>>>(wl2, wr2);          // 6

    // layer 0: c0h = [agg(x) | x], K=384 -> h1 (fp16) into c1h self region
    gather_x<<<NN / 4, dim3(FEA / 4, 4)>>>(x, c0h);
    sage_mma<<<dim3(2, 128), 256, SAGE_SMEM>>>(c0h, 384, w0h, w0l, bl0, HID,
                                               c1h + 256, nullptr);
    // layer 1: c1h = [agg(h1) | h1], K=512 -> h2 into c0h self region
    gather_f16<<<NN / 8, dim3(32, 8)>>>(c1h + 256, c1h);
    sage_mma<<<dim3(2, 128), 256, SAGE_SMEM>>>(c1h, 512, w1h, w1l, bl1, HID,
                                               c0h + 256, nullptr);
    // layer 2: c0h = [agg(h2) | h2], K=512, N padded 1024 -> pool partials
    gather_f16<<<NN / 8, dim3(32, 8)>>>(c0h + 256, c0h);
    sage_mma<<<dim3(8, 128), 256, SAGE_SMEM>>>(c0h, 512, w2h, w2l, bl2, CLS,
                                               nullptr, part);

    reduce_pool<<<(BATCH * CLS + 255) / 256, 256>>>(out);
}

// round 10
// speedup vs baseline: 1.7540x; 1.4089x over previous
#include <cuda_runtime.h>
#include <cuda_fp16.h>
#include <cfloat>

#define NN   8192
#define FEA  192
#define HID  256
#define CLS  1000
#define KNB  9
#define NCAND 16
#define KSTR 512
#define BATCH 16

typedef unsigned int u32;
typedef unsigned short u16;
typedef unsigned long long u64;
typedef __half f16;

// ---------------- scratch ----------------------------------------------------
__device__ float g_sq[NN];
__device__ __half g_Dh[(long long)NN * NN];        // 128 MB approx distances
__device__ int   g_idx[NN * KNB];
__device__ f16   g_c0h[NN * KSTR];                 // cat buffer 0: [agg | self]
__device__ f16   g_c1h[NN * KSTR];                 // cat buffer 1
__device__ f16   g_w0h[256 * 384],  g_w0l[256 * 384];
__device__ f16   g_w1h[256 * 512],  g_w1l[256 * 512];
__device__ f16   g_w2h[1024 * 512], g_w2l[1024 * 512];
__device__ float g_part[1024 * 128];               // layer2 pool partials

// ---------------- helpers ----------------------------------------------------
__device__ __forceinline__ u32 s2u(const void* p) {
    u32 a;
    asm("{.reg .u64 t; cvta.to.shared.u64 t, %1; cvt.u32.u64 %0, t;}" : "=r"(a) : "l"(p));
    return a;
}
__device__ __forceinline__ void cpa16(u32 dst, const void* src) {
    asm volatile("cp.async.cg.shared.global [%0], [%1], 16;" :: "r"(dst), "l"(src));
}
__device__ __forceinline__ void ldsm4(u32* r, u32 addr) {
    asm volatile("ldmatrix.sync.aligned.m8n8.x4.shared.b16 {%0,%1,%2,%3}, [%4];"
        : "=r"(r[0]), "=r"(r[1]), "=r"(r[2]), "=r"(r[3]) : "r"(addr));
}
__device__ __forceinline__ void mma16816(float* c, const u32* a, const u32* b) {
    asm volatile("mma.sync.aligned.m16n8k16.row.col.f32.f16.f16.f32 "
        "{%0,%1,%2,%3},{%4,%5,%6,%7},{%8,%9},{%0,%1,%2,%3};"
        : "+f"(c[0]), "+f"(c[1]), "+f"(c[2]), "+f"(c[3])
        : "r"(a[0]), "r"(a[1]), "r"(a[2]), "r"(a[3]), "r"(b[0]), "r"(b[1]));
}
__device__ __forceinline__ void spltw(float v, f16& h, f16& l) {
    h = __float2half_rn(v);
    l = __float2half_rn(v - __half2float(h));
}

// fp16 tile loader: [128 rows x 32 k] (row stride 40 halfs = 80B)
__device__ __forceinline__ void ldtile(u32 dstb, const f16* g, int row0, int ld, int k0, int t) {
    #pragma unroll
    for (int q = 0; q < 2; q++) {
        int id = t * 2 + q;
        int row = id >> 2, kq = id & 3;
        cpa16(dstb + row * 80 + kq * 16, g + (size_t)(row0 + row) * ld + k0 + kq * 8);
    }
}
// fp16 tile loader: [64 rows x 32 k]
__device__ __forceinline__ void ldtileA64(u32 dstb, const f16* g, int row0, int ld, int k0, int t) {
    int row = t >> 2, kq = t & 3;
    cpa16(dstb + row * 80 + kq * 16, g + (size_t)(row0 + row) * ld + k0 + kq * 8);
}

#define TB 10240     // 128-row fp16 tile
#define ATB 5120     // 64-row fp16 tile
#define SSTG (ATB + 2 * TB)   // sage stage = 25600

// ---------------- small kernels ----------------------------------------------
__global__ void sq_kernel(const float* __restrict__ x) {
    int warp = (blockIdx.x * blockDim.x + threadIdx.x) >> 5;
    int lane = threadIdx.x & 31;
    if (warp >= NN) return;
    const float* r = x + (size_t)warp * FEA;
    float s = 0.f;
    for (int c = lane; c < FEA; c += 32) { float v = r[c]; s += v * v; }
    #pragma unroll
    for (int o = 16; o; o >>= 1) s += __shfl_xor_sync(0xffffffffu, s, o);
    if (lane == 0) g_sq[warp] = s;
}

__global__ void xprep_kernel(const float* __restrict__ x) {
    int g = blockIdx.x * 256 + threadIdx.x;
    if (g >= NN * FEA / 4) return;
    int r = g / 48, c4 = (g % 48) * 4;
    float4 v = *(const float4*)(x + (size_t)r * FEA + c4);
    __half2 p0; p0.x = __float2half_rn(v.x); p0.y = __float2half_rn(v.y);
    __half2 p1; p1.x = __float2half_rn(v.z); p1.y = __float2half_rn(v.w);
    size_t off = (size_t)r * KSTR + 192 + c4;
    *(__half2*)(g_c0h + off)     = p0;
    *(__half2*)(g_c0h + off + 2) = p1;
}

__global__ void wt_build01(const float* __restrict__ Wl0, const float* __restrict__ Wr0,
                           const float* __restrict__ Wl1, const float* __restrict__ Wr1) {
    int layer = blockIdx.y;
    const float* Wl = layer ? Wl1 : Wl0;
    const float* Wr = layer ? Wr1 : Wr0;
    f16* WTh = layer ? g_w1h : g_w0h;
    f16* WTl = layer ? g_w1l : g_w0l;
    int K1 = layer ? 256 : 192;
    int Ktot = 2 * K1;
    int total = 256 * Ktot;
    int idx = blockIdx.x * 256 + threadIdx.x;
    if (idx >= total) return;
    int k = idx % Ktot;
    int n = idx / Ktot;
    float v = (k < K1) ? Wl[(size_t)k * HID + n] : Wr[(size_t)(k - K1) * HID + n];
    f16 h, l; spltw(v, h, l);
    WTh[idx] = h; WTl[idx] = l;
}

__global__ void wt_build2(const float* __restrict__ Wl, const float* __restrict__ Wr) {
    int idx = blockIdx.x * 256 + threadIdx.x;
    if (idx >= 1024 * 512) return;
    int n = idx / 512, k = idx % 512;
    float v = 0.f;
    if (n < CLS) v = (k < 256) ? Wl[(size_t)k * CLS + n] : Wr[(size_t)(k - 256) * CLS + n];
    f16 h, l; spltw(v, h, l);
    g_w2h[idx] = h; g_w2l[idx] = l;
}

// ---------------- fp16 distance screen GEMM (triangular grid) -----------------
__global__ __launch_bounds__(256, 2) void dist_half(const f16* __restrict__ Xh) {
    int tp = blockIdx.x;
    int bj = (int)((sqrtf(8.f * tp + 1.f) - 1.f) * 0.5f);
    while ((bj + 1) * (bj + 2) / 2 <= tp) bj++;
    while (bj * (bj + 1) / 2 > tp) bj--;
    int bi = tp - bj * (bj + 1) / 2;

    extern __shared__ __align__(16) char smem[];
    u32 sb = s2u(smem);
    int t = threadIdx.x, lane = t & 31, warp = t >> 5;
    int wm = warp & 1, wn = warp >> 1;

    float acc[4][4][4] = {};

    const int NC = FEA / 32;   // 6
    ldtile(sb + 0 * TB, Xh, bi * 128, KSTR, 0, t);
    ldtile(sb + 1 * TB, Xh, bj * 128, KSTR, 0, t);
    asm volatile("cp.async.commit_group;");

    for (int c = 0; c < NC; c++) {
        if (c + 1 < NC) {
            u32 bb = sb + ((c + 1) & 1) * 2 * TB;
            int k0 = (c + 1) * 32;
            ldtile(bb + 0 * TB, Xh, bi * 128, KSTR, k0, t);
            ldtile(bb + 1 * TB, Xh, bj * 128, KSTR, k0, t);
            asm volatile("cp.async.commit_group;");
            asm volatile("cp.async.wait_group 1;");
        } else {
            asm volatile("cp.async.wait_group 0;");
        }
        __syncthreads();
        u32 base = sb + (c & 1) * 2 * TB;
        u32 aH = base, bH = base + TB;
        #pragma unroll
        for (int kk = 0; kk < 32; kk += 16) {
            u32 AH[4][4], BH[4][2];
            #pragma unroll
            for (int mt = 0; mt < 4; mt++) {
                u32 ro = (u32)((wm * 64 + mt * 16 + (lane & 15)) * 80 + (kk + (lane >> 4) * 8) * 2);
                ldsm4(AH[mt], aH + ro);
            }
            #pragma unroll
            for (int np = 0; np < 2; np++) {
                u32 ro = (u32)((wn * 32 + np * 16 + ((lane >> 4) * 8) + (lane & 7)) * 80
                               + (kk + ((lane >> 3) & 1) * 8) * 2);
                u32 r[4];
                ldsm4(r, bH + ro);
                BH[2 * np][0] = r[0]; BH[2 * np][1] = r[1];
                BH[2 * np + 1][0] = r[2]; BH[2 * np + 1][1] = r[3];
            }
            #pragma unroll
            for (int mt = 0; mt < 4; mt++)
                #pragma unroll
                for (int nt = 0; nt < 4; nt++)
                    mma16816(acc[mt][nt], AH[mt], BH[nt]);
        }
        __syncthreads();
    }

    u16* sD = (u16*)smem;            // [128][136]
    u16* sT = sD + 128 * 136;
    bool diag = (bi == bj);
    #pragma unroll
    for (int mt = 0; mt < 4; mt++) {
        int rl0 = wm * 64 + mt * 16 + (lane >> 2);
        #pragma unroll
        for (int nt = 0; nt < 4; nt++) {
            int cl = wn * 32 + nt * 8 + (lane & 3) * 2;
            float sqc0 = g_sq[bj * 128 + cl], sqc1 = g_sq[bj * 128 + cl + 1];
            #pragma unroll
            for (int h = 0; h < 2; h++) {
                int rl = rl0 + h * 8;
                float sr = g_sq[bi * 128 + rl];
                float d0 = sr + sqc0 - 2.f * acc[mt][nt][2 * h + 0];
                float d1 = sr + sqc1 - 2.f * acc[mt][nt][2 * h + 1];
                u16 b0 = __half_as_ushort(__float2half_rn(d0));
                u16 b1 = __half_as_ushort(__float2half_rn(d1));
                sD[rl * 136 + cl] = b0;
                sD[rl * 136 + cl + 1] = b1;
                if (!diag) {
                    sT[cl * 136 + rl] = b0;
                    sT[(cl + 1) * 136 + rl] = b1;
                }
            }
        }
    }
    __syncthreads();
    u16* gD = (u16*)g_Dh;
    for (int e = t; e < 128 * 16; e += 256) {
        int r = e >> 4, c8 = (e & 15) * 8;
        uint4 v = *(uint4*)&sD[r * 136 + c8];
        *(uint4*)(gD + (size_t)(bi * 128 + r) * NN + bj * 128 + c8) = v;
    }
    if (!diag) {
        for (int e = t; e < 128 * 16; e += 256) {
            int r = e >> 4, c8 = (e & 15) * 8;
            uint4 v = *(uint4*)&sT[r * 136 + c8];
            *(uint4*)(gD + (size_t)(bj * 128 + r) * NN + bi * 128 + c8) = v;
        }
    }
}

// ---------------- warp-per-row top-16 screen + exact fp32 refine ---------------
__global__ __launch_bounds__(256, 6) void topk_warp(const float* __restrict__ x) {
    int lane = threadIdx.x & 31, wid = threadIdx.x >> 5;
    int row = blockIdx.x * 8 + wid;

    __shared__ int scand[8][NCAND];
    __shared__ float scd[8][NCAND];

    // ---- stream 8192 fp16 values, keep per-lane sorted top-8 packed keys ----
    u32 top[8];
    #pragma unroll
    for (int q = 0; q < 8; q++) top[q] = 0xFFFFFFFFu;

    const uint4* rp = (const uint4*)(g_Dh + (size_t)row * NN);
    for (int i = 0; i < 32; i++) {
        uint4 v = __ldg(rp + i * 32 + lane);
        u32 w[4] = {v.x, v.y, v.z, v.w};
        u32 base = (u32)((i * 32 + lane) * 8);
        #pragma unroll
        for (int p = 0; p < 4; p++) {
            #pragma unroll
            for (int hh = 0; hh < 2; hh++) {
                u32 hb = (w[p] >> (16 * hh)) & 0xFFFFu;
                u32 m = (hb & 0x8000u) ? 0xFFFFu : 0x8000u;
                u32 pk = ((hb ^ m) << 16) | (base + p * 2 + hh);
                if (pk < top[7]) {
                    top[7] = pk;
                    #pragma unroll
                    for (int q = 7; q > 0; q--) {
                        if (top[q] < top[q - 1]) { u32 tt = top[q]; top[q] = top[q - 1]; top[q - 1] = tt; }
                    }
                }
            }
        }
    }

    // ---- extract warp top-16 (16 argmin rounds, lane min = top[0]) ----
    #pragma unroll
    for (int r = 0; r < NCAND; r++) {
        u32 mn = top[0];
        #pragma unroll
        for (int o = 16; o; o >>= 1) mn = min(mn, __shfl_xor_sync(0xffffffffu, mn, o));
        if (top[0] == mn) {
            scand[wid][r] = (int)(mn & 0xFFFFu);
            #pragma unroll
            for (int q = 0; q < 7; q++) top[q] = top[q + 1];
            top[7] = 0xFFFFFFFFu;
        }
        __syncwarp();
    }

    // ---- exact fp32 refine of the 16 candidates ----
    float xi[6];
    const float* xr = x + (size_t)row * FEA;
    #pragma unroll
    for (int q = 0; q < 6; q++) xi[q] = __ldg(xr + q * 32 + lane);
    float sqi = g_sq[row];
    #pragma unroll
    for (int c = 0; c < NCAND; c++) {
        int j = scand[wid][c];
        const float* xj = x + (size_t)j * FEA;
        float s = 0.f;
        #pragma unroll
        for (int q = 0; q < 6; q++) s = fmaf(xi[q], __ldg(xj + q * 32 + lane), s);
        #pragma unroll
        for (int o = 16; o; o >>= 1) s += __shfl_xor_sync(0xffffffffu, s, o);
        if (lane == 0) scd[wid][c] = sqi + g_sq[j] - 2.f * s;
    }
    __syncwarp();

    // ---- exact top-9 of 16 with (dist, idx) lexicographic order ----
    u64 kk = ~0ull;
    if (lane < NCAND) {
        u32 b = __float_as_uint(scd[wid][lane]);
        b ^= (b & 0x80000000u) ? 0xFFFFFFFFu : 0x80000000u;
        kk = ((u64)b << 32) | (u32)scand[wid][lane];
    }
    #pragma unroll
    for (int r = 0; r < KNB; r++) {
        u64 mn = kk;
        #pragma unroll
        for (int o = 16; o; o >>= 1) {
            u64 other = __shfl_xor_sync(0xffffffffu, mn, o);
            mn = other < mn ? other : mn;
        }
        if (lane == 0) g_idx[row * KNB + r] = (int)(mn & 0xFFFFFFFFull);
        if (kk == mn) kk = ~0ull;
        __syncwarp();
    }
}

// ---------------- gather + mean from fp32 x (layer 0) --------------------------
__global__ void gather_x(const float* __restrict__ x, f16* __restrict__ oh) {
    int row = blockIdx.x * 4 + threadIdx.y;
    int c4 = threadIdx.x * 4;
    const int* idp = g_idx + row * KNB;
    float4 s = make_float4(0.f, 0.f, 0.f, 0.f);
    #pragma unroll
    for (int j = 0; j < KNB; j++) {
        float4 v = __ldg((const float4*)(x + (size_t)idp[j] * FEA + c4));
        s.x += v.x; s.y += v.y; s.z += v.z; s.w += v.w;
    }
    const float inv = 1.0f / 9.0f;
    size_t off = (size_t)row * KSTR + c4;
    __half2 p0; p0.x = __float2half_rn(s.x * inv); p0.y = __float2half_rn(s.y * inv);
    __half2 p1; p1.x = __float2half_rn(s.z * inv); p1.y = __float2half_rn(s.w * inv);
    *(__half2*)(oh + off)     = p0;
    *(__half2*)(oh + off + 2) = p1;
}

// ---------------- gather + mean from fp16 cat self (layers 1,2) ----------------
__global__ void gather_f16(const f16* __restrict__ cat_self, f16* __restrict__ cat_agg) {
    int row = blockIdx.x * 8 + threadIdx.y;
    int c8 = threadIdx.x * 8;
    const int* idp = g_idx + row * KNB;
    float s[8] = {0.f, 0.f, 0.f, 0.f, 0.f, 0.f, 0.f, 0.f};
    #pragma unroll
    for (int j = 0; j < KNB; j++) {
        uint4 v = __ldg((const uint4*)(cat_self + (size_t)idp[j] * KSTR + c8));
        u32 w[4] = {v.x, v.y, v.z, v.w};
        #pragma unroll
        for (int p = 0; p < 4; p++) {
            float2 f = __half22float2(*(__half2*)&w[p]);
            s[2 * p] += f.x; s[2 * p + 1] += f.y;
        }
    }
    const float inv = 1.0f / 9.0f;
    u32 out[4];
    #pragma unroll
    for (int p = 0; p < 4; p++) {
        __half2 h; h.x = __float2half_rn(s[2 * p] * inv); h.y = __float2half_rn(s[2 * p + 1] * inv);
        out[p] = *(u32*)&h;
    }
    *(uint4*)(cat_agg + (size_t)row * KSTR + c8) = *(uint4*)out;
}

// ---------------- SAGE dual-GEMM, M64 tiles, 3 CTAs/SM --------------------------
__global__ __launch_bounds__(256, 3) void sage_mma(
    const f16* __restrict__ Ah, int Ktot,
    const f16* __restrict__ Bh, const f16* __restrict__ Bl,
    const float* __restrict__ bias, int Nbias,
    f16* __restrict__ Sh, float* __restrict__ part)
{
    int bn = blockIdx.x, bm = blockIdx.y;
    extern __shared__ __align__(16) char smem[];
    u32 sb = s2u(smem);
    int t = threadIdx.x, lane = t & 31, warp = t >> 5;
    int wm = warp & 1, wn = warp >> 1;

    float acc[2][4][4] = {};

    int nc = Ktot / 32;
    ldtileA64(sb + 0, Ah, bm * 64, KSTR, 0, t);
    ldtile(sb + ATB, Bh, bn * 128, Ktot, 0, t);
    ldtile(sb + ATB + TB, Bl, bn * 128, Ktot, 0, t);
    asm volatile("cp.async.commit_group;");

    for (int c = 0; c < nc; c++) {
        if (c + 1 < nc) {
            u32 bb = sb + ((c + 1) & 1) * SSTG;
            int k0 = (c + 1) * 32;
            ldtileA64(bb + 0, Ah, bm * 64, KSTR, k0, t);
            ldtile(bb + ATB, Bh, bn * 128, Ktot, k0, t);
            ldtile(bb + ATB + TB, Bl, bn * 128, Ktot, k0, t);
            asm volatile("cp.async.commit_group;");
            asm volatile("cp.async.wait_group 1;");
        } else {
            asm volatile("cp.async.wait_group 0;");
        }
        __syncthreads();
        u32 base = sb + (c & 1) * SSTG;
        u32 aH = base, bH = base + ATB, bL = base + ATB + TB;
        #pragma unroll
        for (int kk = 0; kk < 32; kk += 16) {
            u32 AH[2][4], BH[4][2], BL[4][2];
            #pragma unroll
            for (int mt = 0; mt < 2; mt++) {
                u32 ro = (u32)((wm * 32 + mt * 16 + (lane & 15)) * 80 + (kk + (lane >> 4) * 8) * 2);
                ldsm4(AH[mt], aH + ro);
            }
            #pragma unroll
            for (int np = 0; np < 2; np++) {
                u32 ro = (u32)((wn * 32 + np * 16 + ((lane >> 4) * 8) + (lane & 7)) * 80
                               + (kk + ((lane >> 3) & 1) * 8) * 2);
                u32 r[4];
                ldsm4(r, bH + ro);
                BH[2 * np][0] = r[0]; BH[2 * np][1] = r[1];
                BH[2 * np + 1][0] = r[2]; BH[2 * np + 1][1] = r[3];
                ldsm4(r, bL + ro);
                BL[2 * np][0] = r[0]; BL[2 * np][1] = r[1];
                BL[2 * np + 1][0] = r[2]; BL[2 * np + 1][1] = r[3];
            }
            #pragma unroll
            for (int mt = 0; mt < 2; mt++)
                #pragma unroll
                for (int nt = 0; nt < 4; nt++) {
                    mma16816(acc[mt][nt], AH[mt], BH[nt]);
                    mma16816(acc[mt][nt], AH[mt], BL[nt]);
                }
        }
        __syncthreads();
    }

    if (Sh) {
        #pragma unroll
        for (int mt = 0; mt < 2; mt++) {
            int rl0 = wm * 32 + mt * 16 + (lane >> 2);
            #pragma unroll
            for (int nt = 0; nt < 4; nt++) {
                int cl = wn * 32 + nt * 8 + (lane & 3) * 2;
                int col = bn * 128 + cl;
                float b0 = bias[col], b1 = bias[col + 1];
                #pragma unroll
                for (int h = 0; h < 2; h++) {
                    int row = bm * 64 + rl0 + h * 8;
                    float v0 = fmaxf(acc[mt][nt][2 * h + 0] + b0, 0.f);
                    float v1 = fmaxf(acc[mt][nt][2 * h + 1] + b1, 0.f);
                    __half2 p; p.x = __float2half_rn(v0); p.y = __float2half_rn(v1);
                    *(__half2*)(Sh + (size_t)row * KSTR + col) = p;
                }
            }
        }
    } else {
        float* sCol = (float*)smem;
        if (t < 128) sCol[t] = 0.f;
        __syncthreads();
        #pragma unroll
        for (int nt = 0; nt < 4; nt++) {
            int cl = wn * 32 + nt * 8 + (lane & 3) * 2;
            int col = bn * 128 + cl;
            float b0 = (col < Nbias) ? bias[col] : 0.f;
            float b1 = (col + 1 < Nbias) ? bias[col + 1] : 0.f;
            float p0 = 0.f, p1 = 0.f;
            #pragma unroll
            for (int mt = 0; mt < 2; mt++)
                #pragma unroll
                for (int h = 0; h < 2; h++) {
                    p0 += fmaxf(acc[mt][nt][2 * h + 0] + b0, 0.f);
                    p1 += fmaxf(acc[mt][nt][2 * h + 1] + b1, 0.f);
                }
            atomicAdd(&sCol[cl], p0);
            atomicAdd(&sCol[cl + 1], p1);
        }
        __syncthreads();
        if (t < 128) part[(size_t)(bm * 8 + bn) * 128 + t] = sCol[t];
    }
}

// ---------------- pool reduce ----------------------------------------------------
__global__ void reduce_pool(float* __restrict__ out) {
    int idx = blockIdx.x * 256 + threadIdx.x;
    if (idx >= BATCH * CLS) return;
    int b = idx / CLS, o = idx % CLS;
    int bn = o >> 7, c = o & 127;
    float s = 0.f;
    #pragma unroll
    for (int q = 0; q < 8; q++)
        s += g_part[(size_t)((b * 8 + q) * 8 + bn) * 128 + c];
    out[idx] = s * (1.0f / 512.0f);
}

// ---------------- launch --------------------------------------------------------
#define DIST_SMEM (128 * 136 * 2 * 2)   // 69632
#define SAGE_SMEM (2 * SSTG)            // 51200

extern "C" void kernel_launch(void* const* d_in, const int* in_sizes, int n_in,
                              void* d_out, int out_size) {
    const float* x   = (const float*)d_in[0];
    const float* wl0 = (const float*)d_in[1];
    const float* bl0 = (const float*)d_in[2];
    const float* wr0 = (const float*)d_in[3];
    const float* wl1 = (const float*)d_in[4];
    const float* bl1 = (const float*)d_in[5];
    const float* wr1 = (const float*)d_in[6];
    const float* wl2 = (const float*)d_in[7];
    const float* bl2 = (const float*)d_in[8];
    const float* wr2 = (const float*)d_in[9];
    float* out = (float*)d_out;

    f16 *c0h, *c1h, *w0h, *w0l, *w1h, *w1l, *w2h, *w2l;
    float* part;
    cudaGetSymbolAddress((void**)&c0h, g_c0h);
    cudaGetSymbolAddress((void**)&c1h, g_c1h);
    cudaGetSymbolAddress((void**)&w0h, g_w0h);
    cudaGetSymbolAddress((void**)&w0l, g_w0l);
    cudaGetSymbolAddress((void**)&w1h, g_w1h);
    cudaGetSymbolAddress((void**)&w1l, g_w1l);
    cudaGetSymbolAddress((void**)&w2h, g_w2h);
    cudaGetSymbolAddress((void**)&w2l, g_w2l);
    cudaGetSymbolAddress((void**)&part, g_part);

    cudaFuncSetAttribute(dist_half, cudaFuncAttributeMaxDynamicSharedMemorySize, DIST_SMEM);
    cudaFuncSetAttribute(sage_mma, cudaFuncAttributeMaxDynamicSharedMemorySize, SAGE_SMEM);

    sq_kernel<<<NN / 8, 256>>>(x);                                   // 1
    xprep_kernel<<<(NN * FEA / 4 + 255) / 256, 256>>>(x);            // 2
    dist_half<<<2080, 256, DIST_SMEM>>>(c0h + 192);                  // 3
    topk_warp<<<NN / 8, 256>>>(x);                                   // 4 (profiled)
    wt_build01<<<dim3(512, 2), 256>>>(wl0, wr0, wl1, wr1);           // 5
    wt_build2<<<(1024 * 512 + 255) / 256, 256>>>(wl2, wr2);          // 6

    // layer 0: c0h = [agg(x) | x], K=384 -> h1 (fp16) into c1h self region
    gather_x<<<NN / 4, dim3(FEA / 4, 4)>>>(x, c0h);
    sage_mma<<<dim3(2, 128), 256, SAGE_SMEM>>>(c0h, 384, w0h, w0l, bl0, HID,
                                               c1h + 256, nullptr);
    // layer 1: c1h = [agg(h1) | h1], K=512 -> h2 into c0h self region
    gather_f16<<<NN / 8, dim3(32, 8)>>>(c1h + 256, c1h);
    sage_mma<<<dim3(2, 128), 256, SAGE_SMEM>>>(c1h, 512, w1h, w1l, bl1, HID,
                                               c0h + 256, nullptr);
    // layer 2: c0h = [agg(h2) | h2], K=512, N padded 1024 -> pool partials
    gather_f16<<<NN / 8, dim3(32, 8)>>>(c0h + 256, c0h);
    sage_mma<<<dim3(8, 128), 256, SAGE_SMEM>>>(c0h, 512, w2h, w2l, bl2, CLS,
                                               nullptr, part);

    reduce_pool<<<(BATCH * CLS + 255) / 256, 256>>>(out);
}